// round 10
// baseline (speedup 1.0000x reference)
#include <cuda_runtime.h>
#include <cuda_bf16.h>
#include <cstdint>

#define N_NODES 100000
#define N_FEATS 512
#define HIDDEN  64
#define N_CLS   40
#define N_EDGES 1600000
#define SCAN_B  1024
#define NBLK    ((N_NODES + SCAN_B - 1) / SCAN_B)   // 98

// ---------------- scratch ----------------
__device__ float g_dinv[N_NODES];
__device__ short g_q1[(size_t)N_NODES * HIDDEN];   // quantized h1
__device__ float g_s1[N_NODES];                    // h1 row scales
__device__ float g_out1[(size_t)N_NODES * HIDDEN];
__device__ float g_h2[(size_t)N_NODES * N_CLS];
__device__ short g_q2[(size_t)N_NODES * N_CLS];    // quantized h2
__device__ float g_s2[N_NODES];
__device__ float g_w2t[HIDDEN * N_CLS];            // [64][40]
__device__ __nv_bfloat16 g_w1hi[HIDDEN * N_FEATS];
__device__ __nv_bfloat16 g_w1lo[HIDDEN * N_FEATS];
__device__ int   g_deg[N_NODES];
__device__ int   g_rowptr[N_NODES];
__device__ int   g_cursor[N_NODES];
__device__ int   g_srcs[N_EDGES];
__device__ int   g_bsum[NBLK];

// ---------------- helpers ----------------
__device__ __forceinline__ uint32_t smem_u32(const void* p) {
    uint32_t a;
    asm("{ .reg .u64 t; cvta.to.shared.u64 t, %1; cvt.u32.u64 %0, t; }" : "=r"(a) : "l"(p));
    return a;
}
__device__ __forceinline__ void ldm_x4(uint32_t& r0, uint32_t& r1, uint32_t& r2,
                                       uint32_t& r3, uint32_t addr) {
    asm volatile("ldmatrix.sync.aligned.m8n8.x4.shared.b16 {%0,%1,%2,%3}, [%4];"
                 : "=r"(r0), "=r"(r1), "=r"(r2), "=r"(r3) : "r"(addr));
}
__device__ __forceinline__ void mma16816(float* d, const uint32_t* a,
                                         uint32_t b0, uint32_t b1) {
    asm volatile(
        "mma.sync.aligned.m16n8k16.row.col.f32.bf16.bf16.f32 "
        "{%0,%1,%2,%3}, {%4,%5,%6,%7}, {%8,%9}, {%0,%1,%2,%3};"
        : "+f"(d[0]), "+f"(d[1]), "+f"(d[2]), "+f"(d[3])
        : "r"(a[0]), "r"(a[1]), "r"(a[2]), "r"(a[3]), "r"(b0), "r"(b1));
}
__device__ __forceinline__ void cp16(uint32_t dst, const void* src) {
    asm volatile("cp.async.cg.shared.global [%0], [%1], 16;" :: "r"(dst), "l"(src));
}
__device__ __forceinline__ uint32_t pack2(float a, float b) {
    int ia = __float2int_rn(a), ib = __float2int_rn(b);
    return (uint32_t)(unsigned short)(short)ia | ((uint32_t)(unsigned short)(short)ib << 16);
}

// ---------------- fused prep ----------------
__global__ void k_prep(const float* __restrict__ W1, const float* __restrict__ W2) {
    int i = blockIdx.x * blockDim.x + threadIdx.x;
    if (i < HIDDEN * N_FEATS) {
        float v = W1[i];
        __nv_bfloat16 h = __float2bfloat16(v);
        g_w1hi[i] = h;
        g_w1lo[i] = __float2bfloat16(v - __bfloat162float(h));
    }
    if (i < HIDDEN * N_CLS) {
        int k = i / N_CLS, j = i - k * N_CLS;
        g_w2t[i] = W2[j * HIDDEN + k];
    }
    if (i < N_NODES) g_deg[i] = 0;
}

// ---------------- CSR build ----------------
__global__ void k_deg_count(const int* __restrict__ ei) {
    int e = (blockIdx.x * blockDim.x + threadIdx.x) * 4;
    if (e >= N_EDGES) return;
    int4 d = *(const int4*)(ei + N_EDGES + e);
    atomicAdd(&g_deg[d.x], 1);
    atomicAdd(&g_deg[d.y], 1);
    atomicAdd(&g_deg[d.z], 1);
    atomicAdd(&g_deg[d.w], 1);
}
__global__ void __launch_bounds__(SCAN_B) k_scan1() {
    int i = blockIdx.x * SCAN_B + threadIdx.x;
    int lane = threadIdx.x & 31, wid = threadIdx.x >> 5;
    int v = (i < N_NODES) ? g_deg[i] : 0;
#pragma unroll
    for (int o = 16; o > 0; o >>= 1) v += __shfl_down_sync(0xffffffffu, v, o);
    __shared__ int ws[32];
    if (lane == 0) ws[wid] = v;
    __syncthreads();
    if (wid == 0) {
        int t = ws[lane];
#pragma unroll
        for (int o = 16; o > 0; o >>= 1) t += __shfl_down_sync(0xffffffffu, t, o);
        if (lane == 0) g_bsum[blockIdx.x] = t;
    }
}
__global__ void __launch_bounds__(SCAN_B) k_scan3() {
    const int tid = threadIdx.x;
    const int lane = tid & 31, wid = tid >> 5;
    __shared__ int ws[32];
    __shared__ int s_boff;

    int bv = (tid < blockIdx.x && tid < NBLK) ? g_bsum[tid] : 0;
#pragma unroll
    for (int o = 16; o > 0; o >>= 1) bv += __shfl_down_sync(0xffffffffu, bv, o);
    if (lane == 0) ws[wid] = bv;
    __syncthreads();
    if (wid == 0) {
        int t = ws[lane];
#pragma unroll
        for (int o = 16; o > 0; o >>= 1) t += __shfl_down_sync(0xffffffffu, t, o);
        if (lane == 0) s_boff = t;
    }
    __syncthreads();

    int i = blockIdx.x * SCAN_B + tid;
    int d = (i < N_NODES) ? g_deg[i] : 0;
    int v = d;
#pragma unroll
    for (int o = 1; o < 32; o <<= 1) {
        int n = __shfl_up_sync(0xffffffffu, v, o);
        if (lane >= o) v += n;
    }
    __syncthreads();
    if (lane == 31) ws[wid] = v;
    __syncthreads();
    if (wid == 0) {
        int t = ws[lane];
#pragma unroll
        for (int o = 1; o < 32; o <<= 1) {
            int n = __shfl_up_sync(0xffffffffu, t, o);
            if (lane >= o) t += n;
        }
        ws[lane] = t;
    }
    __syncthreads();
    int excl = s_boff + ((wid > 0) ? ws[wid - 1] : 0) + (v - d);
    if (i < N_NODES) {
        g_rowptr[i] = excl;
        g_cursor[i] = excl;
        g_dinv[i]   = rsqrtf((float)d + 1.0f);
    }
}
__global__ void k_csr_scatter(const int* __restrict__ ei) {
    int e = (blockIdx.x * blockDim.x + threadIdx.x) * 4;
    if (e >= N_EDGES) return;
    int4 s = *(const int4*)(ei + e);
    int4 d = *(const int4*)(ei + N_EDGES + e);
    int p0 = atomicAdd(&g_cursor[d.x], 1); g_srcs[p0] = s.x;
    int p1 = atomicAdd(&g_cursor[d.y], 1); g_srcs[p1] = s.y;
    int p2 = atomicAdd(&g_cursor[d.z], 1); g_srcs[p2] = s.z;
    int p3 = atomicAdd(&g_cursor[d.w], 1); g_srcs[p3] = s.w;
}

// ---------------- GEMM1: pipelined bf16 split MMA, int16-quantized epilogue --
#define A_OFF(buf, sp) ((size_t)((buf) * 2 + (sp)) * 18432)
#define B_OFF(buf, sp) (73728 + (size_t)((buf) * 2 + (sp)) * 9216)
#define GEMM1_SMEM (73728 + 4 * 9216)   // 110592 B

__device__ __forceinline__ void g1_cvt_store(const float4* xr, char* smem, int buf,
                                             int tid) {
    char* ah = smem + A_OFF(buf, 0);
    char* al = smem + A_OFF(buf, 1);
#pragma unroll
    for (int i = 0; i < 8; i++) {
        int idx = tid + i * 256;
        int row = idx >> 4;
        int kq  = (idx & 15) * 4;
        float4 v = xr[i];
        __nv_bfloat16 h0 = __float2bfloat16(v.x), h1 = __float2bfloat16(v.y);
        __nv_bfloat16 h2 = __float2bfloat16(v.z), h3 = __float2bfloat16(v.w);
        __nv_bfloat16 l0 = __float2bfloat16(v.x - __bfloat162float(h0));
        __nv_bfloat16 l1 = __float2bfloat16(v.y - __bfloat162float(h1));
        __nv_bfloat16 l2 = __float2bfloat16(v.z - __bfloat162float(h2));
        __nv_bfloat16 l3 = __float2bfloat16(v.w - __bfloat162float(h3));
        __nv_bfloat162 hp0 = __halves2bfloat162(h0, h1), hp1 = __halves2bfloat162(h2, h3);
        __nv_bfloat162 lp0 = __halves2bfloat162(l0, l1), lp1 = __halves2bfloat162(l2, l3);
        uint2 hv = make_uint2(*(uint32_t*)&hp0, *(uint32_t*)&hp1);
        uint2 lv = make_uint2(*(uint32_t*)&lp0, *(uint32_t*)&lp1);
        size_t off = ((size_t)row * 72 + kq) * 2;
        *(uint2*)(ah + off) = hv;
        *(uint2*)(al + off) = lv;
    }
}

__device__ __forceinline__ void g1_ldg_x(const float* __restrict__ x, float4* xr,
                                         int rowBase, int c, int tid) {
#pragma unroll
    for (int i = 0; i < 8; i++) {
        int idx = tid + i * 256;
        int row = idx >> 4;
        int kq  = (idx & 15) * 4;
        int grow = rowBase + row;
        xr[i] = make_float4(0.f, 0.f, 0.f, 0.f);
        if (grow < N_NODES)
            xr[i] = *(const float4*)(x + (size_t)grow * N_FEATS + c * 64 + kq);
    }
}

__device__ __forceinline__ void g1_cpasync_w(const __nv_bfloat16* __restrict__ wh,
                                             const __nv_bfloat16* __restrict__ wl,
                                             uint32_t sb, int c, int buf, int tid) {
#pragma unroll
    for (int i = 0; i < 2; i++) {
        int idx = tid + i * 256;
        int n = idx >> 3, j = idx & 7;
        uint32_t off = (uint32_t)(((size_t)n * 72 + j * 8) * 2);
        cp16(sb + (uint32_t)B_OFF(buf, 0) + off, wh + (size_t)n * N_FEATS + c * 64 + j * 8);
        cp16(sb + (uint32_t)B_OFF(buf, 1) + off, wl + (size_t)n * N_FEATS + c * 64 + j * 8);
    }
    asm volatile("cp.async.commit_group;" ::: "memory");
}

__global__ void __launch_bounds__(256) k_gemm1_mma(const float* __restrict__ x,
                                                   const __nv_bfloat16* __restrict__ wh,
                                                   const __nv_bfloat16* __restrict__ wl) {
    extern __shared__ __align__(16) char smem[];
    const uint32_t sb = smem_u32(smem);
    const int tid = threadIdx.x, w = tid >> 5, lane = tid & 31;
    const int rowBase = blockIdx.x * 128;

    float acc[8][4];
#pragma unroll
    for (int s = 0; s < 8; s++)
#pragma unroll
        for (int j = 0; j < 4; j++) acc[s][j] = 0.f;

    {
        float4 xr[8];
        g1_ldg_x(x, xr, rowBase, 0, tid);
        g1_cpasync_w(wh, wl, sb, 0, 0, tid);
        g1_cvt_store(xr, smem, 0, tid);
        asm volatile("cp.async.wait_group 0;" ::: "memory");
    }
    __syncthreads();

    const int arow = w * 16 + (lane & 15);
    const int acolbase = ((lane >> 4) & 1) * 8;
    const int brow = (lane & 7) + ((lane >> 4) & 1) * 8;
    const int bcolbase = ((lane >> 3) & 1) * 8;

    int buf = 0;
    for (int c = 0; c < 8; c++) {
        float4 xr[8];
        if (c < 7) {
            g1_ldg_x(x, xr, rowBase, c + 1, tid);
            g1_cpasync_w(wh, wl, sb, c + 1, buf ^ 1, tid);
        }

        const uint32_t aH = sb + (uint32_t)A_OFF(buf, 0);
        const uint32_t aL = sb + (uint32_t)A_OFF(buf, 1);
        const uint32_t bH = sb + (uint32_t)B_OFF(buf, 0);
        const uint32_t bL = sb + (uint32_t)B_OFF(buf, 1);

#pragma unroll
        for (int t = 0; t < 4; t++) {
            int kk = t * 16;
            uint32_t ahr[4], alr[4];
            uint32_t aoff = (uint32_t)((arow * 72 + kk + acolbase) * 2);
            ldm_x4(ahr[0], ahr[1], ahr[2], ahr[3], aH + aoff);
            ldm_x4(alr[0], alr[1], alr[2], alr[3], aL + aoff);
#pragma unroll
            for (int p = 0; p < 4; p++) {
                int n0 = p * 16;
                uint32_t boff = (uint32_t)((((n0 + brow) * 72) + kk + bcolbase) * 2);
                uint32_t bh0, bh1, bh2, bh3, bl0, bl1, bl2, bl3;
                ldm_x4(bh0, bh1, bh2, bh3, bH + boff);
                ldm_x4(bl0, bl1, bl2, bl3, bL + boff);
                mma16816(acc[2 * p],     ahr, bh0, bh1);
                mma16816(acc[2 * p],     ahr, bl0, bl1);
                mma16816(acc[2 * p],     alr, bh0, bh1);
                mma16816(acc[2 * p + 1], ahr, bh2, bh3);
                mma16816(acc[2 * p + 1], ahr, bl2, bl3);
                mma16816(acc[2 * p + 1], alr, bh2, bh3);
            }
        }

        if (c < 7) {
            g1_cvt_store(xr, smem, buf ^ 1, tid);
            asm volatile("cp.async.wait_group 0;" ::: "memory");
        }
        __syncthreads();
        buf ^= 1;
    }

    // ---- epilogue: per-row int16 quantization (rows r0 and r0+8) ----
    const int r0 = rowBase + w * 16 + (lane >> 2);
    const int cb = (lane & 3) * 2;

    float m0 = 0.f, m1 = 0.f;
#pragma unroll
    for (int s = 0; s < 8; s++) {
        m0 = fmaxf(m0, fmaxf(fabsf(acc[s][0]), fabsf(acc[s][1])));
        m1 = fmaxf(m1, fmaxf(fabsf(acc[s][2]), fabsf(acc[s][3])));
    }
#pragma unroll
    for (int o = 1; o <= 2; o <<= 1) {
        m0 = fmaxf(m0, __shfl_xor_sync(0xffffffffu, m0, o));
        m1 = fmaxf(m1, __shfl_xor_sync(0xffffffffu, m1, o));
    }
    const float inv0 = m0 > 0.f ? 32767.f / m0 : 0.f;
    const float inv1 = m1 > 0.f ? 32767.f / m1 : 0.f;

    if (r0 < N_NODES) {
        if ((lane & 3) == 0) g_s1[r0] = m0 * (1.f / 32767.f);
        char* base = (char*)g_q1 + (size_t)r0 * HIDDEN * 2;
#pragma unroll
        for (int s = 0; s < 8; s++)
            *(uint32_t*)(base + (s * 8 + cb) * 2) = pack2(acc[s][0] * inv0, acc[s][1] * inv0);
    }
    if (r0 + 8 < N_NODES) {
        if ((lane & 3) == 0) g_s1[r0 + 8] = m1 * (1.f / 32767.f);
        char* base = (char*)g_q1 + (size_t)(r0 + 8) * HIDDEN * 2;
#pragma unroll
        for (int s = 0; s < 8; s++)
            *(uint32_t*)(base + (s * 8 + cb) * 2) = pack2(acc[s][2] * inv1, acc[s][3] * inv1);
    }
}

// ---------------- layer-1 aggregation over int16 ----------------
__global__ void __launch_bounds__(256) k_agg1_gather(const float* __restrict__ b1,
                                                     float* __restrict__ out1) {
    const int tid  = threadIdx.x;
    const int g    = tid >> 4;
    const int lane = tid & 15;
    const int n    = blockIdx.x * 16 + g;   // N_NODES % 16 == 0 -> always valid

    const float dn = g_dinv[n];
    const int start = g_rowptr[n];
    const int end   = start + g_deg[n];

    short4 qn = *(const short4*)(g_q1 + (size_t)n * HIDDEN + lane * 4);
    float c0 = g_s1[n] * dn * dn;
    float4 acc = make_float4(qn.x * c0, qn.y * c0, qn.z * c0, qn.w * c0);

    int e = start;
    for (; e + 4 <= end; e += 4) {
        int s0 = g_srcs[e], s1 = g_srcs[e + 1], s2 = g_srcs[e + 2], s3 = g_srcs[e + 3];
        float c1 = g_s1[s0] * g_dinv[s0] * dn;
        float c2 = g_s1[s1] * g_dinv[s1] * dn;
        float c3 = g_s1[s2] * g_dinv[s2] * dn;
        float c4 = g_s1[s3] * g_dinv[s3] * dn;
        short4 m0 = *(const short4*)(g_q1 + (size_t)s0 * HIDDEN + lane * 4);
        short4 m1 = *(const short4*)(g_q1 + (size_t)s1 * HIDDEN + lane * 4);
        short4 m2 = *(const short4*)(g_q1 + (size_t)s2 * HIDDEN + lane * 4);
        short4 m3 = *(const short4*)(g_q1 + (size_t)s3 * HIDDEN + lane * 4);
        acc.x += m0.x * c1 + m1.x * c2 + m2.x * c3 + m3.x * c4;
        acc.y += m0.y * c1 + m1.y * c2 + m2.y * c3 + m3.y * c4;
        acc.z += m0.z * c1 + m1.z * c2 + m2.z * c3 + m3.z * c4;
        acc.w += m0.w * c1 + m1.w * c2 + m2.w * c3 + m3.w * c4;
    }
    for (; e < end; e++) {
        int src = g_srcs[e];
        float c = g_s1[src] * g_dinv[src] * dn;
        short4 m = *(const short4*)(g_q1 + (size_t)src * HIDDEN + lane * 4);
        acc.x += m.x * c; acc.y += m.y * c; acc.z += m.z * c; acc.w += m.w * c;
    }
    float4 bb = *(const float4*)(b1 + lane * 4);
    acc.x = fmaxf(acc.x + bb.x, 0.f);
    acc.y = fmaxf(acc.y + bb.y, 0.f);
    acc.z = fmaxf(acc.z + bb.z, 0.f);
    acc.w = fmaxf(acc.w + bb.w, 0.f);
    *(float4*)(out1 + (size_t)n * HIDDEN + lane * 4) = acc;
}

// ---------------- GEMM2: h2[N][40] = out1[N][64] @ W2^T ----------------
__global__ void __launch_bounds__(256) k_gemm2(const float* __restrict__ h1r,
                                               float* __restrict__ h2) {
    __shared__ float xs[128][65];
    __shared__ float wsT[HIDDEN * N_CLS];
    const int tid = threadIdx.x;
    const int r = tid & 127;
    const int q = tid >> 7;
    const int rowBase = blockIdx.x * 128;

#pragma unroll
    for (int m = 0; m < 8; m++) {
        int idx4 = tid + m * 256;
        int row = idx4 >> 4, kq = (idx4 & 15) * 4;
        int grow = rowBase + row;
        float4 v = make_float4(0.f, 0.f, 0.f, 0.f);
        if (grow < N_NODES)
            v = *(const float4*)(h1r + (size_t)grow * HIDDEN + kq);
        xs[row][kq + 0] = v.x; xs[row][kq + 1] = v.y;
        xs[row][kq + 2] = v.z; xs[row][kq + 3] = v.w;
    }
    for (int idx4 = tid; idx4 < 640; idx4 += 256)
        ((float4*)wsT)[idx4] = ((const float4*)g_w2t)[idx4];
    __syncthreads();

    unsigned long long acc[10];
#pragma unroll
    for (int i = 0; i < 10; i++) acc[i] = 0ull;

#pragma unroll 4
    for (int k = 0; k < HIDDEN; k++) {
        float xv = xs[r][k];
        unsigned long long xx;
        asm("mov.b64 %0, {%1, %1};" : "=l"(xx) : "f"(xv));
        const unsigned long long* wrow =
            (const unsigned long long*)(wsT + k * N_CLS + q * 20);
#pragma unroll
        for (int c = 0; c < 10; c++) {
            unsigned long long w2 = wrow[c];
            asm("fma.rn.f32x2 %0, %1, %2, %0;" : "+l"(acc[c]) : "l"(w2), "l"(xx));
        }
    }

    int grow = rowBase + r;
    if (grow < N_NODES) {
        float* dst = h2 + (size_t)grow * N_CLS + q * 20;
#pragma unroll
        for (int c = 0; c < 10; c++) {
            float a0, a1;
            asm("mov.b64 {%0,%1}, %2;" : "=f"(a0), "=f"(a1) : "l"(acc[c]));
            *(float2*)(dst + c * 2) = make_float2(a0, a1);
        }
    }
}

// ---------------- quantize h2 -> q2/s2 ----------------
__global__ void __launch_bounds__(256) k_quant2(const float* __restrict__ h2) {
    const int tid  = threadIdx.x;
    const int g    = tid >> 4;
    const int lane = tid & 15;
    const int n    = blockIdx.x * 16 + g;   // exact grid

    float4 v = make_float4(0.f, 0.f, 0.f, 0.f);
    if (lane < 10)
        v = *(const float4*)(h2 + (size_t)n * N_CLS + lane * 4);
    float m = fmaxf(fmaxf(fabsf(v.x), fabsf(v.y)), fmaxf(fabsf(v.z), fabsf(v.w)));
    const unsigned gm = 0xffffu << (threadIdx.x & 16);
#pragma unroll
    for (int o = 1; o <= 8; o <<= 1)
        m = fmaxf(m, __shfl_xor_sync(gm, m, o));
    if (lane == 0) g_s2[n] = m * (1.f / 32767.f);
    float inv = m > 0.f ? 32767.f / m : 0.f;
    if (lane < 10) {
        short4 q;
        q.x = (short)__float2int_rn(v.x * inv);
        q.y = (short)__float2int_rn(v.y * inv);
        q.z = (short)__float2int_rn(v.z * inv);
        q.w = (short)__float2int_rn(v.w * inv);
        *(short4*)(g_q2 + (size_t)n * N_CLS + lane * 4) = q;
    }
}

// ---------------- layer-2 aggregation over int16 ----------------
__global__ void __launch_bounds__(256) k_agg2_gather(const float* __restrict__ b2,
                                                     float* __restrict__ out) {
    const int tid  = threadIdx.x;
    const int g    = tid >> 4;
    const int lane = tid & 15;
    const int n    = blockIdx.x * 16 + g;
    if (lane >= 10) return;

    const float dn = g_dinv[n];
    const int start = g_rowptr[n];
    const int end   = start + g_deg[n];

    short4 qn = *(const short4*)(g_q2 + (size_t)n * N_CLS + lane * 4);
    float c0 = g_s2[n] * dn * dn;
    float4 acc = make_float4(qn.x * c0, qn.y * c0, qn.z * c0, qn.w * c0);

    int e = start;
    for (; e + 4 <= end; e += 4) {
        int s0 = g_srcs[e], s1 = g_srcs[e + 1], s2 = g_srcs[e + 2], s3 = g_srcs[e + 3];
        float c1 = g_s2[s0] * g_dinv[s0] * dn;
        float c2 = g_s2[s1] * g_dinv[s1] * dn;
        float c3 = g_s2[s2] * g_dinv[s2] * dn;
        float c4 = g_s2[s3] * g_dinv[s3] * dn;
        short4 m0 = *(const short4*)(g_q2 + (size_t)s0 * N_CLS + lane * 4);
        short4 m1 = *(const short4*)(g_q2 + (size_t)s1 * N_CLS + lane * 4);
        short4 m2 = *(const short4*)(g_q2 + (size_t)s2 * N_CLS + lane * 4);
        short4 m3 = *(const short4*)(g_q2 + (size_t)s3 * N_CLS + lane * 4);
        acc.x += m0.x * c1 + m1.x * c2 + m2.x * c3 + m3.x * c4;
        acc.y += m0.y * c1 + m1.y * c2 + m2.y * c3 + m3.y * c4;
        acc.z += m0.z * c1 + m1.z * c2 + m2.z * c3 + m3.z * c4;
        acc.w += m0.w * c1 + m1.w * c2 + m2.w * c3 + m3.w * c4;
    }
    for (; e < end; e++) {
        int src = g_srcs[e];
        float c = g_s2[src] * g_dinv[src] * dn;
        short4 m = *(const short4*)(g_q2 + (size_t)src * N_CLS + lane * 4);
        acc.x += m.x * c; acc.y += m.y * c; acc.z += m.z * c; acc.w += m.w * c;
    }
    float4 bb = *(const float4*)(b2 + lane * 4);
    acc.x += bb.x; acc.y += bb.y; acc.z += bb.z; acc.w += bb.w;
    *(float4*)(out + (size_t)n * N_CLS + lane * 4) = acc;
}

// ---------------- launch ----------------
extern "C" void kernel_launch(void* const* d_in, const int* in_sizes, int n_in,
                              void* d_out, int out_size) {
    const float* x  = (const float*)d_in[0];
    const int*   ei = (const int*)d_in[1];
    const float* W1 = (const float*)d_in[2];
    const float* b1 = (const float*)d_in[3];
    const float* W2 = (const float*)d_in[4];
    const float* b2 = (const float*)d_in[5];
    float* out = (float*)d_out;

    float *out1, *h2;
    __nv_bfloat16 *wh, *wl;
    cudaGetSymbolAddress((void**)&out1, g_out1);
    cudaGetSymbolAddress((void**)&h2,   g_h2);
    cudaGetSymbolAddress((void**)&wh,   g_w1hi);
    cudaGetSymbolAddress((void**)&wl,   g_w1lo);

    k_prep<<<(N_NODES + 255) / 256, 256>>>(W1, W2);

    k_deg_count<<<(N_EDGES / 4 + 255) / 256, 256>>>(ei);
    k_scan1<<<NBLK, SCAN_B>>>();
    k_scan3<<<NBLK, SCAN_B>>>();
    k_csr_scatter<<<(N_EDGES / 4 + 255) / 256, 256>>>(ei);

    cudaFuncSetAttribute(k_gemm1_mma, cudaFuncAttributeMaxDynamicSharedMemorySize,
                         GEMM1_SMEM);
    k_gemm1_mma<<<(N_NODES + 127) / 128, 256, GEMM1_SMEM>>>(x, wh, wl);
    k_agg1_gather<<<N_NODES / 16, 256>>>(b1, out1);

    k_gemm2<<<(N_NODES + 127) / 128, 256>>>(out1, h2);
    k_quant2<<<N_NODES / 16, 256>>>(h2);
    k_agg2_gather<<<N_NODES / 16, 256>>>(b2, out);
}

// round 11
// speedup vs baseline: 1.0317x; 1.0317x over previous
#include <cuda_runtime.h>
#include <cuda_bf16.h>
#include <cstdint>

#define N_NODES 100000
#define N_FEATS 512
#define HIDDEN  64
#define N_CLS   40
#define N_EDGES 1600000
#define SCAN_B  1024
#define NBLK    ((N_NODES + SCAN_B - 1) / SCAN_B)   // 98
#define PSRC    (N_EDGES + 3 * N_NODES)              // padded srcs capacity

// ---------------- scratch ----------------
__device__ float g_dinv[N_NODES];
__device__ float g_h1s[(size_t)(N_NODES + 1) * HIDDEN];  // dinv-scaled; last row zero
__device__ float g_out1[(size_t)N_NODES * HIDDEN];
__device__ float g_h2s[(size_t)(N_NODES + 1) * N_CLS];   // dinv-scaled; last row zero
__device__ float g_w2t[HIDDEN * N_CLS];                  // [64][40]
__device__ __nv_bfloat16 g_w1hi[HIDDEN * N_FEATS];
__device__ __nv_bfloat16 g_w1lo[HIDDEN * N_FEATS];
__device__ int   g_deg[N_NODES];
__device__ int   g_rowptr[N_NODES];
__device__ int   g_cursor[N_NODES];
__device__ int   g_srcs[PSRC];
__device__ int   g_bsum[NBLK];

// ---------------- helpers ----------------
__device__ __forceinline__ uint32_t smem_u32(const void* p) {
    uint32_t a;
    asm("{ .reg .u64 t; cvta.to.shared.u64 t, %1; cvt.u32.u64 %0, t; }" : "=r"(a) : "l"(p));
    return a;
}
__device__ __forceinline__ void ldm_x4(uint32_t& r0, uint32_t& r1, uint32_t& r2,
                                       uint32_t& r3, uint32_t addr) {
    asm volatile("ldmatrix.sync.aligned.m8n8.x4.shared.b16 {%0,%1,%2,%3}, [%4];"
                 : "=r"(r0), "=r"(r1), "=r"(r2), "=r"(r3) : "r"(addr));
}
__device__ __forceinline__ void mma16816(float* d, const uint32_t* a,
                                         uint32_t b0, uint32_t b1) {
    asm volatile(
        "mma.sync.aligned.m16n8k16.row.col.f32.bf16.bf16.f32 "
        "{%0,%1,%2,%3}, {%4,%5,%6,%7}, {%8,%9}, {%0,%1,%2,%3};"
        : "+f"(d[0]), "+f"(d[1]), "+f"(d[2]), "+f"(d[3])
        : "r"(a[0]), "r"(a[1]), "r"(a[2]), "r"(a[3]), "r"(b0), "r"(b1));
}
__device__ __forceinline__ void cp16(uint32_t dst, const void* src) {
    asm volatile("cp.async.cg.shared.global [%0], [%1], 16;" :: "r"(dst), "l"(src));
}

// ---------------- fused prep ----------------
__global__ void k_prep(const float* __restrict__ W1, const float* __restrict__ W2) {
    int i = blockIdx.x * blockDim.x + threadIdx.x;
    if (i < HIDDEN * N_FEATS) {
        float v = W1[i];
        __nv_bfloat16 h = __float2bfloat16(v);
        g_w1hi[i] = h;
        g_w1lo[i] = __float2bfloat16(v - __bfloat162float(h));
    }
    if (i < HIDDEN * N_CLS) {
        int k = i / N_CLS, j = i - k * N_CLS;
        g_w2t[i] = W2[j * HIDDEN + k];
    }
    if (i < N_NODES) g_deg[i] = 0;
}

// ---------------- CSR build (4-aligned segments, sentinel padding) ----------
__global__ void k_deg_count(const int* __restrict__ ei) {
    int e = (blockIdx.x * blockDim.x + threadIdx.x) * 4;
    if (e >= N_EDGES) return;
    int4 d = *(const int4*)(ei + N_EDGES + e);
    atomicAdd(&g_deg[d.x], 1);
    atomicAdd(&g_deg[d.y], 1);
    atomicAdd(&g_deg[d.z], 1);
    atomicAdd(&g_deg[d.w], 1);
}
__global__ void __launch_bounds__(SCAN_B) k_scan1() {
    int i = blockIdx.x * SCAN_B + threadIdx.x;
    int lane = threadIdx.x & 31, wid = threadIdx.x >> 5;
    int v = 0;
    if (i < N_NODES) { int d = g_deg[i]; v = (d + 3) & ~3; }
#pragma unroll
    for (int o = 16; o > 0; o >>= 1) v += __shfl_down_sync(0xffffffffu, v, o);
    __shared__ int ws[32];
    if (lane == 0) ws[wid] = v;
    __syncthreads();
    if (wid == 0) {
        int t = ws[lane];
#pragma unroll
        for (int o = 16; o > 0; o >>= 1) t += __shfl_down_sync(0xffffffffu, t, o);
        if (lane == 0) g_bsum[blockIdx.x] = t;
    }
}
__global__ void __launch_bounds__(SCAN_B) k_scan3() {
    const int tid = threadIdx.x;
    const int lane = tid & 31, wid = tid >> 5;
    __shared__ int ws[32];
    __shared__ int s_boff;

    int bv = (tid < blockIdx.x && tid < NBLK) ? g_bsum[tid] : 0;
#pragma unroll
    for (int o = 16; o > 0; o >>= 1) bv += __shfl_down_sync(0xffffffffu, bv, o);
    if (lane == 0) ws[wid] = bv;
    __syncthreads();
    if (wid == 0) {
        int t = ws[lane];
#pragma unroll
        for (int o = 16; o > 0; o >>= 1) t += __shfl_down_sync(0xffffffffu, t, o);
        if (lane == 0) s_boff = t;
    }
    __syncthreads();

    int i = blockIdx.x * SCAN_B + tid;
    int d = 0, pd = 0;
    if (i < N_NODES) { d = g_deg[i]; pd = (d + 3) & ~3; }
    int v = pd;
#pragma unroll
    for (int o = 1; o < 32; o <<= 1) {
        int n = __shfl_up_sync(0xffffffffu, v, o);
        if (lane >= o) v += n;
    }
    __syncthreads();
    if (lane == 31) ws[wid] = v;
    __syncthreads();
    if (wid == 0) {
        int t = ws[lane];
#pragma unroll
        for (int o = 1; o < 32; o <<= 1) {
            int n = __shfl_up_sync(0xffffffffu, t, o);
            if (lane >= o) t += n;
        }
        ws[lane] = t;
    }
    __syncthreads();
    int excl = s_boff + ((wid > 0) ? ws[wid - 1] : 0) + (v - pd);
    if (i < N_NODES) {
        g_rowptr[i] = excl;
        g_cursor[i] = excl;
        g_dinv[i]   = rsqrtf((float)d + 1.0f);
        for (int p = d; p < pd; p++) g_srcs[excl + p] = N_NODES;  // sentinel
    }
}
__global__ void k_csr_scatter(const int* __restrict__ ei) {
    int e = (blockIdx.x * blockDim.x + threadIdx.x) * 4;
    if (e >= N_EDGES) return;
    int4 s = *(const int4*)(ei + e);
    int4 d = *(const int4*)(ei + N_EDGES + e);
    int p0 = atomicAdd(&g_cursor[d.x], 1); g_srcs[p0] = s.x;
    int p1 = atomicAdd(&g_cursor[d.y], 1); g_srcs[p1] = s.y;
    int p2 = atomicAdd(&g_cursor[d.z], 1); g_srcs[p2] = s.z;
    int p3 = atomicAdd(&g_cursor[d.w], 1); g_srcs[p3] = s.w;
}

// ---------------- GEMM1: pipelined bf16 split MMA, dinv-scaled epilogue -----
#define A_OFF(buf, sp) ((size_t)((buf) * 2 + (sp)) * 18432)
#define B_OFF(buf, sp) (73728 + (size_t)((buf) * 2 + (sp)) * 9216)
#define GEMM1_SMEM (73728 + 4 * 9216)   // 110592 B

__device__ __forceinline__ void g1_cvt_store(const float4* xr, char* smem, int buf,
                                             int tid) {
    char* ah = smem + A_OFF(buf, 0);
    char* al = smem + A_OFF(buf, 1);
#pragma unroll
    for (int i = 0; i < 8; i++) {
        int idx = tid + i * 256;
        int row = idx >> 4;
        int kq  = (idx & 15) * 4;
        float4 v = xr[i];
        __nv_bfloat16 h0 = __float2bfloat16(v.x), h1 = __float2bfloat16(v.y);
        __nv_bfloat16 h2 = __float2bfloat16(v.z), h3 = __float2bfloat16(v.w);
        __nv_bfloat16 l0 = __float2bfloat16(v.x - __bfloat162float(h0));
        __nv_bfloat16 l1 = __float2bfloat16(v.y - __bfloat162float(h1));
        __nv_bfloat16 l2 = __float2bfloat16(v.z - __bfloat162float(h2));
        __nv_bfloat16 l3 = __float2bfloat16(v.w - __bfloat162float(h3));
        __nv_bfloat162 hp0 = __halves2bfloat162(h0, h1), hp1 = __halves2bfloat162(h2, h3);
        __nv_bfloat162 lp0 = __halves2bfloat162(l0, l1), lp1 = __halves2bfloat162(l2, l3);
        uint2 hv = make_uint2(*(uint32_t*)&hp0, *(uint32_t*)&hp1);
        uint2 lv = make_uint2(*(uint32_t*)&lp0, *(uint32_t*)&lp1);
        size_t off = ((size_t)row * 72 + kq) * 2;
        *(uint2*)(ah + off) = hv;
        *(uint2*)(al + off) = lv;
    }
}

__device__ __forceinline__ void g1_ldg_x(const float* __restrict__ x, float4* xr,
                                         int rowBase, int c, int tid) {
#pragma unroll
    for (int i = 0; i < 8; i++) {
        int idx = tid + i * 256;
        int row = idx >> 4;
        int kq  = (idx & 15) * 4;
        int grow = rowBase + row;
        xr[i] = make_float4(0.f, 0.f, 0.f, 0.f);
        if (grow < N_NODES)
            xr[i] = *(const float4*)(x + (size_t)grow * N_FEATS + c * 64 + kq);
    }
}

__device__ __forceinline__ void g1_cpasync_w(const __nv_bfloat16* __restrict__ wh,
                                             const __nv_bfloat16* __restrict__ wl,
                                             uint32_t sb, int c, int buf, int tid) {
#pragma unroll
    for (int i = 0; i < 2; i++) {
        int idx = tid + i * 256;
        int n = idx >> 3, j = idx & 7;
        uint32_t off = (uint32_t)(((size_t)n * 72 + j * 8) * 2);
        cp16(sb + (uint32_t)B_OFF(buf, 0) + off, wh + (size_t)n * N_FEATS + c * 64 + j * 8);
        cp16(sb + (uint32_t)B_OFF(buf, 1) + off, wl + (size_t)n * N_FEATS + c * 64 + j * 8);
    }
    asm volatile("cp.async.commit_group;" ::: "memory");
}

__global__ void __launch_bounds__(256) k_gemm1_mma(const float* __restrict__ x,
                                                   const __nv_bfloat16* __restrict__ wh,
                                                   const __nv_bfloat16* __restrict__ wl) {
    extern __shared__ __align__(16) char smem[];
    const uint32_t sb = smem_u32(smem);
    const int tid = threadIdx.x, w = tid >> 5, lane = tid & 31;
    const int rowBase = blockIdx.x * 128;

    float acc[8][4];
#pragma unroll
    for (int s = 0; s < 8; s++)
#pragma unroll
        for (int j = 0; j < 4; j++) acc[s][j] = 0.f;

    {
        float4 xr[8];
        g1_ldg_x(x, xr, rowBase, 0, tid);
        g1_cpasync_w(wh, wl, sb, 0, 0, tid);
        g1_cvt_store(xr, smem, 0, tid);
        asm volatile("cp.async.wait_group 0;" ::: "memory");
    }
    __syncthreads();

    const int arow = w * 16 + (lane & 15);
    const int acolbase = ((lane >> 4) & 1) * 8;
    const int brow = (lane & 7) + ((lane >> 4) & 1) * 8;
    const int bcolbase = ((lane >> 3) & 1) * 8;

    int buf = 0;
    for (int c = 0; c < 8; c++) {
        float4 xr[8];
        if (c < 7) {
            g1_ldg_x(x, xr, rowBase, c + 1, tid);
            g1_cpasync_w(wh, wl, sb, c + 1, buf ^ 1, tid);
        }

        const uint32_t aH = sb + (uint32_t)A_OFF(buf, 0);
        const uint32_t aL = sb + (uint32_t)A_OFF(buf, 1);
        const uint32_t bH = sb + (uint32_t)B_OFF(buf, 0);
        const uint32_t bL = sb + (uint32_t)B_OFF(buf, 1);

#pragma unroll
        for (int t = 0; t < 4; t++) {
            int kk = t * 16;
            uint32_t ahr[4], alr[4];
            uint32_t aoff = (uint32_t)((arow * 72 + kk + acolbase) * 2);
            ldm_x4(ahr[0], ahr[1], ahr[2], ahr[3], aH + aoff);
            ldm_x4(alr[0], alr[1], alr[2], alr[3], aL + aoff);
#pragma unroll
            for (int p = 0; p < 4; p++) {
                int n0 = p * 16;
                uint32_t boff = (uint32_t)((((n0 + brow) * 72) + kk + bcolbase) * 2);
                uint32_t bh0, bh1, bh2, bh3, bl0, bl1, bl2, bl3;
                ldm_x4(bh0, bh1, bh2, bh3, bH + boff);
                ldm_x4(bl0, bl1, bl2, bl3, bL + boff);
                mma16816(acc[2 * p],     ahr, bh0, bh1);
                mma16816(acc[2 * p],     ahr, bl0, bl1);
                mma16816(acc[2 * p],     alr, bh0, bh1);
                mma16816(acc[2 * p + 1], ahr, bh2, bh3);
                mma16816(acc[2 * p + 1], ahr, bl2, bl3);
                mma16816(acc[2 * p + 1], alr, bh2, bh3);
            }
        }

        if (c < 7) {
            g1_cvt_store(xr, smem, buf ^ 1, tid);
            asm volatile("cp.async.wait_group 0;" ::: "memory");
        }
        __syncthreads();
        buf ^= 1;
    }

    // epilogue: store rows pre-scaled by dinv[row]
    const int r0 = rowBase + w * 16 + (lane >> 2);
    const int cb = (lane & 3) * 2;
    if (r0 < N_NODES) {
        float d0 = g_dinv[r0];
#pragma unroll
        for (int s = 0; s < 8; s++)
            *(float2*)(g_h1s + (size_t)r0 * HIDDEN + s * 8 + cb) =
                make_float2(acc[s][0] * d0, acc[s][1] * d0);
    }
    if (r0 + 8 < N_NODES) {
        float d1 = g_dinv[r0 + 8];
#pragma unroll
        for (int s = 0; s < 8; s++)
            *(float2*)(g_h1s + (size_t)(r0 + 8) * HIDDEN + s * 8 + cb) =
                make_float2(acc[s][2] * d1, acc[s][3] * d1);
    }
}

// ---------------- layer-1 aggregation: pure-add gather over pre-scaled rows --
__global__ void __launch_bounds__(256) k_agg1_gather(const float* __restrict__ b1,
                                                     float* __restrict__ out1) {
    const int tid  = threadIdx.x;
    const int g    = tid >> 4;
    const int lane = tid & 15;
    const int n    = blockIdx.x * 16 + g;   // N_NODES % 16 == 0

    const float dn = g_dinv[n];
    const int deg = g_deg[n];
    const int start = g_rowptr[n];
    const int pend  = start + ((deg + 3) & ~3);

    float4 acc = *(const float4*)(g_h1s + (size_t)n * HIDDEN + lane * 4);

    for (int e = start; e < pend; e += 4) {
        int4 s = *(const int4*)(g_srcs + e);
        float4 m0 = *(const float4*)(g_h1s + (size_t)s.x * HIDDEN + lane * 4);
        float4 m1 = *(const float4*)(g_h1s + (size_t)s.y * HIDDEN + lane * 4);
        float4 m2 = *(const float4*)(g_h1s + (size_t)s.z * HIDDEN + lane * 4);
        float4 m3 = *(const float4*)(g_h1s + (size_t)s.w * HIDDEN + lane * 4);
        acc.x += m0.x + m1.x + m2.x + m3.x;
        acc.y += m0.y + m1.y + m2.y + m3.y;
        acc.z += m0.z + m1.z + m2.z + m3.z;
        acc.w += m0.w + m1.w + m2.w + m3.w;
    }
    float4 bb = *(const float4*)(b1 + lane * 4);
    acc.x = fmaxf(acc.x * dn + bb.x, 0.f);
    acc.y = fmaxf(acc.y * dn + bb.y, 0.f);
    acc.z = fmaxf(acc.z * dn + bb.z, 0.f);
    acc.w = fmaxf(acc.w * dn + bb.w, 0.f);
    *(float4*)(out1 + (size_t)n * HIDDEN + lane * 4) = acc;
}

// ---------------- GEMM2: h2s[N][40] = (out1 @ W2^T) * dinv[row] -------------
__global__ void __launch_bounds__(256) k_gemm2(const float* __restrict__ h1r,
                                               float* __restrict__ h2s) {
    __shared__ float xs[128][65];
    __shared__ float wsT[HIDDEN * N_CLS];
    const int tid = threadIdx.x;
    const int r = tid & 127;
    const int q = tid >> 7;
    const int rowBase = blockIdx.x * 128;

#pragma unroll
    for (int m = 0; m < 8; m++) {
        int idx4 = tid + m * 256;
        int row = idx4 >> 4, kq = (idx4 & 15) * 4;
        int grow = rowBase + row;
        float4 v = make_float4(0.f, 0.f, 0.f, 0.f);
        if (grow < N_NODES)
            v = *(const float4*)(h1r + (size_t)grow * HIDDEN + kq);
        xs[row][kq + 0] = v.x; xs[row][kq + 1] = v.y;
        xs[row][kq + 2] = v.z; xs[row][kq + 3] = v.w;
    }
    for (int idx4 = tid; idx4 < 640; idx4 += 256)
        ((float4*)wsT)[idx4] = ((const float4*)g_w2t)[idx4];
    __syncthreads();

    unsigned long long acc[10];
#pragma unroll
    for (int i = 0; i < 10; i++) acc[i] = 0ull;

#pragma unroll 4
    for (int k = 0; k < HIDDEN; k++) {
        float xv = xs[r][k];
        unsigned long long xx;
        asm("mov.b64 %0, {%1, %1};" : "=l"(xx) : "f"(xv));
        const unsigned long long* wrow =
            (const unsigned long long*)(wsT + k * N_CLS + q * 20);
#pragma unroll
        for (int c = 0; c < 10; c++) {
            unsigned long long w2 = wrow[c];
            asm("fma.rn.f32x2 %0, %1, %2, %0;" : "+l"(acc[c]) : "l"(w2), "l"(xx));
        }
    }

    int grow = rowBase + r;
    if (grow < N_NODES) {
        float dv = g_dinv[grow];
        float* dst = h2s + (size_t)grow * N_CLS + q * 20;
#pragma unroll
        for (int c = 0; c < 10; c++) {
            float a0, a1;
            asm("mov.b64 {%0,%1}, %2;" : "=f"(a0), "=f"(a1) : "l"(acc[c]));
            *(float2*)(dst + c * 2) = make_float2(a0 * dv, a1 * dv);
        }
    }
}

// ---------------- layer-2 aggregation: pure-add gather ----------------
__global__ void __launch_bounds__(256) k_agg2_gather(const float* __restrict__ b2,
                                                     float* __restrict__ out) {
    const int tid  = threadIdx.x;
    const int g    = tid >> 4;
    const int lane = tid & 15;
    const int n    = blockIdx.x * 16 + g;
    if (lane >= 10) return;

    const float dn = g_dinv[n];
    const int deg = g_deg[n];
    const int start = g_rowptr[n];
    const int pend  = start + ((deg + 3) & ~3);

    float4 acc = *(const float4*)(g_h2s + (size_t)n * N_CLS + lane * 4);

    for (int e = start; e < pend; e += 4) {
        int4 s = *(const int4*)(g_srcs + e);
        float4 m0 = *(const float4*)(g_h2s + (size_t)s.x * N_CLS + lane * 4);
        float4 m1 = *(const float4*)(g_h2s + (size_t)s.y * N_CLS + lane * 4);
        float4 m2 = *(const float4*)(g_h2s + (size_t)s.z * N_CLS + lane * 4);
        float4 m3 = *(const float4*)(g_h2s + (size_t)s.w * N_CLS + lane * 4);
        acc.x += m0.x + m1.x + m2.x + m3.x;
        acc.y += m0.y + m1.y + m2.y + m3.y;
        acc.z += m0.z + m1.z + m2.z + m3.z;
        acc.w += m0.w + m1.w + m2.w + m3.w;
    }
    float4 bb = *(const float4*)(b2 + lane * 4);
    acc.x = acc.x * dn + bb.x;
    acc.y = acc.y * dn + bb.y;
    acc.z = acc.z * dn + bb.z;
    acc.w = acc.w * dn + bb.w;
    *(float4*)(out + (size_t)n * N_CLS + lane * 4) = acc;
}

// ---------------- launch ----------------
extern "C" void kernel_launch(void* const* d_in, const int* in_sizes, int n_in,
                              void* d_out, int out_size) {
    const float* x  = (const float*)d_in[0];
    const int*   ei = (const int*)d_in[1];
    const float* W1 = (const float*)d_in[2];
    const float* b1 = (const float*)d_in[3];
    const float* W2 = (const float*)d_in[4];
    const float* b2 = (const float*)d_in[5];
    float* out = (float*)d_out;

    float *out1, *h2s;
    __nv_bfloat16 *wh, *wl;
    cudaGetSymbolAddress((void**)&out1, g_out1);
    cudaGetSymbolAddress((void**)&h2s,  g_h2s);
    cudaGetSymbolAddress((void**)&wh,   g_w1hi);
    cudaGetSymbolAddress((void**)&wl,   g_w1lo);

    k_prep<<<(N_NODES + 255) / 256, 256>>>(W1, W2);

    k_deg_count<<<(N_EDGES / 4 + 255) / 256, 256>>>(ei);
    k_scan1<<<NBLK, SCAN_B>>>();
    k_scan3<<<NBLK, SCAN_B>>>();
    k_csr_scatter<<<(N_EDGES / 4 + 255) / 256, 256>>>(ei);

    cudaFuncSetAttribute(k_gemm1_mma, cudaFuncAttributeMaxDynamicSharedMemorySize,
                         GEMM1_SMEM);
    k_gemm1_mma<<<(N_NODES + 127) / 128, 256, GEMM1_SMEM>>>(x, wh, wl);
    k_agg1_gather<<<N_NODES / 16, 256>>>(b1, out1);

    k_gemm2<<<(N_NODES + 127) / 128, 256>>>(out1, h2s);
    k_agg2_gather<<<N_NODES / 16, 256>>>(b2, out);
}

// round 12
// speedup vs baseline: 1.0332x; 1.0014x over previous
#include <cuda_runtime.h>
#include <cuda_bf16.h>
#include <cstdint>

#define N_NODES 100000
#define N_FEATS 512
#define HIDDEN  64
#define N_CLS   40
#define N_EDGES 1600000
#define SCAN_B  1024
#define NBLK    ((N_NODES + SCAN_B - 1) / SCAN_B)   // 98

// ---------------- scratch ----------------
__device__ float g_dinv[N_NODES];
__device__ float g_h1[(size_t)N_NODES * HIDDEN];
__device__ float g_out1[(size_t)N_NODES * HIDDEN];
__device__ float g_h2[(size_t)N_NODES * N_CLS];
__device__ float g_w2t[HIDDEN * N_CLS];            // [64][40]
__device__ __nv_bfloat16 g_w1hi[HIDDEN * N_FEATS];
__device__ __nv_bfloat16 g_w1lo[HIDDEN * N_FEATS];
__device__ int   g_deg[N_NODES];
__device__ int   g_rowptr[N_NODES];
__device__ int   g_cursor[N_NODES];
__device__ int   g_srcs[N_EDGES];
__device__ int   g_bsum[NBLK];

// ---------------- helpers ----------------
__device__ __forceinline__ uint32_t smem_u32(const void* p) {
    uint32_t a;
    asm("{ .reg .u64 t; cvta.to.shared.u64 t, %1; cvt.u32.u64 %0, t; }" : "=r"(a) : "l"(p));
    return a;
}
__device__ __forceinline__ void ldm_x4(uint32_t& r0, uint32_t& r1, uint32_t& r2,
                                       uint32_t& r3, uint32_t addr) {
    asm volatile("ldmatrix.sync.aligned.m8n8.x4.shared.b16 {%0,%1,%2,%3}, [%4];"
                 : "=r"(r0), "=r"(r1), "=r"(r2), "=r"(r3) : "r"(addr));
}
__device__ __forceinline__ void mma16816(float* d, const uint32_t* a,
                                         uint32_t b0, uint32_t b1) {
    asm volatile(
        "mma.sync.aligned.m16n8k16.row.col.f32.bf16.bf16.f32 "
        "{%0,%1,%2,%3}, {%4,%5,%6,%7}, {%8,%9}, {%0,%1,%2,%3};"
        : "+f"(d[0]), "+f"(d[1]), "+f"(d[2]), "+f"(d[3])
        : "r"(a[0]), "r"(a[1]), "r"(a[2]), "r"(a[3]), "r"(b0), "r"(b1));
}
__device__ __forceinline__ void cp16(uint32_t dst, const void* src) {
    asm volatile("cp.async.cg.shared.global [%0], [%1], 16;" :: "r"(dst), "l"(src));
}

// ---------------- fused prep ----------------
__global__ void k_prep(const float* __restrict__ W1, const float* __restrict__ W2) {
    int i = blockIdx.x * blockDim.x + threadIdx.x;
    if (i < HIDDEN * N_FEATS) {
        float v = W1[i];
        __nv_bfloat16 h = __float2bfloat16(v);
        g_w1hi[i] = h;
        g_w1lo[i] = __float2bfloat16(v - __bfloat162float(h));
    }
    if (i < HIDDEN * N_CLS) {
        int k = i / N_CLS, j = i - k * N_CLS;
        g_w2t[i] = W2[j * HIDDEN + k];
    }
    if (i < N_NODES) g_deg[i] = 0;
}

// ---------------- CSR build ----------------
__global__ void k_deg_count(const int* __restrict__ ei) {
    int e = (blockIdx.x * blockDim.x + threadIdx.x) * 4;
    if (e >= N_EDGES) return;
    int4 d = *(const int4*)(ei + N_EDGES + e);
    atomicAdd(&g_deg[d.x], 1);
    atomicAdd(&g_deg[d.y], 1);
    atomicAdd(&g_deg[d.z], 1);
    atomicAdd(&g_deg[d.w], 1);
}
__global__ void __launch_bounds__(SCAN_B) k_scan1() {
    int i = blockIdx.x * SCAN_B + threadIdx.x;
    int lane = threadIdx.x & 31, wid = threadIdx.x >> 5;
    int v = (i < N_NODES) ? g_deg[i] : 0;
#pragma unroll
    for (int o = 16; o > 0; o >>= 1) v += __shfl_down_sync(0xffffffffu, v, o);
    __shared__ int ws[32];
    if (lane == 0) ws[wid] = v;
    __syncthreads();
    if (wid == 0) {
        int t = ws[lane];
#pragma unroll
        for (int o = 16; o > 0; o >>= 1) t += __shfl_down_sync(0xffffffffu, t, o);
        if (lane == 0) g_bsum[blockIdx.x] = t;
    }
}
__global__ void __launch_bounds__(SCAN_B) k_scan3() {
    const int tid = threadIdx.x;
    const int lane = tid & 31, wid = tid >> 5;
    __shared__ int ws[32];
    __shared__ int s_boff;

    int bv = (tid < blockIdx.x && tid < NBLK) ? g_bsum[tid] : 0;
#pragma unroll
    for (int o = 16; o > 0; o >>= 1) bv += __shfl_down_sync(0xffffffffu, bv, o);
    if (lane == 0) ws[wid] = bv;
    __syncthreads();
    if (wid == 0) {
        int t = ws[lane];
#pragma unroll
        for (int o = 16; o > 0; o >>= 1) t += __shfl_down_sync(0xffffffffu, t, o);
        if (lane == 0) s_boff = t;
    }
    __syncthreads();

    int i = blockIdx.x * SCAN_B + tid;
    int d = (i < N_NODES) ? g_deg[i] : 0;
    int v = d;
#pragma unroll
    for (int o = 1; o < 32; o <<= 1) {
        int n = __shfl_up_sync(0xffffffffu, v, o);
        if (lane >= o) v += n;
    }
    __syncthreads();
    if (lane == 31) ws[wid] = v;
    __syncthreads();
    if (wid == 0) {
        int t = ws[lane];
#pragma unroll
        for (int o = 1; o < 32; o <<= 1) {
            int n = __shfl_up_sync(0xffffffffu, t, o);
            if (lane >= o) t += n;
        }
        ws[lane] = t;
    }
    __syncthreads();
    int excl = s_boff + ((wid > 0) ? ws[wid - 1] : 0) + (v - d);
    if (i < N_NODES) {
        g_rowptr[i] = excl;
        g_cursor[i] = excl;
        g_dinv[i]   = rsqrtf((float)d + 1.0f);
    }
}
__global__ void k_csr_scatter(const int* __restrict__ ei) {
    int e = (blockIdx.x * blockDim.x + threadIdx.x) * 4;
    if (e >= N_EDGES) return;
    int4 s = *(const int4*)(ei + e);
    int4 d = *(const int4*)(ei + N_EDGES + e);
    int p0 = atomicAdd(&g_cursor[d.x], 1); g_srcs[p0] = s.x;
    int p1 = atomicAdd(&g_cursor[d.y], 1); g_srcs[p1] = s.y;
    int p2 = atomicAdd(&g_cursor[d.z], 1); g_srcs[p2] = s.z;
    int p3 = atomicAdd(&g_cursor[d.w], 1); g_srcs[p3] = s.w;
}

// ---------------- GEMM1: pipelined bf16 split MMA (R9 champion) -------------
#define A_OFF(buf, sp) ((size_t)((buf) * 2 + (sp)) * 18432)
#define B_OFF(buf, sp) (73728 + (size_t)((buf) * 2 + (sp)) * 9216)
#define GEMM1_SMEM (73728 + 4 * 9216)   // 110592 B

__device__ __forceinline__ void g1_cvt_store(const float4* xr, char* smem, int buf,
                                             int tid) {
    char* ah = smem + A_OFF(buf, 0);
    char* al = smem + A_OFF(buf, 1);
#pragma unroll
    for (int i = 0; i < 8; i++) {
        int idx = tid + i * 256;
        int row = idx >> 4;
        int kq  = (idx & 15) * 4;
        float4 v = xr[i];
        __nv_bfloat16 h0 = __float2bfloat16(v.x), h1 = __float2bfloat16(v.y);
        __nv_bfloat16 h2 = __float2bfloat16(v.z), h3 = __float2bfloat16(v.w);
        __nv_bfloat16 l0 = __float2bfloat16(v.x - __bfloat162float(h0));
        __nv_bfloat16 l1 = __float2bfloat16(v.y - __bfloat162float(h1));
        __nv_bfloat16 l2 = __float2bfloat16(v.z - __bfloat162float(h2));
        __nv_bfloat16 l3 = __float2bfloat16(v.w - __bfloat162float(h3));
        __nv_bfloat162 hp0 = __halves2bfloat162(h0, h1), hp1 = __halves2bfloat162(h2, h3);
        __nv_bfloat162 lp0 = __halves2bfloat162(l0, l1), lp1 = __halves2bfloat162(l2, l3);
        uint2 hv = make_uint2(*(uint32_t*)&hp0, *(uint32_t*)&hp1);
        uint2 lv = make_uint2(*(uint32_t*)&lp0, *(uint32_t*)&lp1);
        size_t off = ((size_t)row * 72 + kq) * 2;
        *(uint2*)(ah + off) = hv;
        *(uint2*)(al + off) = lv;
    }
}

__device__ __forceinline__ void g1_ldg_x(const float* __restrict__ x, float4* xr,
                                         int rowBase, int c, int tid) {
#pragma unroll
    for (int i = 0; i < 8; i++) {
        int idx = tid + i * 256;
        int row = idx >> 4;
        int kq  = (idx & 15) * 4;
        int grow = rowBase + row;
        xr[i] = make_float4(0.f, 0.f, 0.f, 0.f);
        if (grow < N_NODES)
            xr[i] = *(const float4*)(x + (size_t)grow * N_FEATS + c * 64 + kq);
    }
}

__device__ __forceinline__ void g1_cpasync_w(const __nv_bfloat16* __restrict__ wh,
                                             const __nv_bfloat16* __restrict__ wl,
                                             uint32_t sb, int c, int buf, int tid) {
#pragma unroll
    for (int i = 0; i < 2; i++) {
        int idx = tid + i * 256;
        int n = idx >> 3, j = idx & 7;
        uint32_t off = (uint32_t)(((size_t)n * 72 + j * 8) * 2);
        cp16(sb + (uint32_t)B_OFF(buf, 0) + off, wh + (size_t)n * N_FEATS + c * 64 + j * 8);
        cp16(sb + (uint32_t)B_OFF(buf, 1) + off, wl + (size_t)n * N_FEATS + c * 64 + j * 8);
    }
    asm volatile("cp.async.commit_group;" ::: "memory");
}

__global__ void __launch_bounds__(256) k_gemm1_mma(const float* __restrict__ x,
                                                   const __nv_bfloat16* __restrict__ wh,
                                                   const __nv_bfloat16* __restrict__ wl) {
    extern __shared__ __align__(16) char smem[];
    const uint32_t sb = smem_u32(smem);
    const int tid = threadIdx.x, w = tid >> 5, lane = tid & 31;
    const int rowBase = blockIdx.x * 128;

    float acc[8][4];
#pragma unroll
    for (int s = 0; s < 8; s++)
#pragma unroll
        for (int j = 0; j < 4; j++) acc[s][j] = 0.f;

    {
        float4 xr[8];
        g1_ldg_x(x, xr, rowBase, 0, tid);
        g1_cpasync_w(wh, wl, sb, 0, 0, tid);
        g1_cvt_store(xr, smem, 0, tid);
        asm volatile("cp.async.wait_group 0;" ::: "memory");
    }
    __syncthreads();

    const int arow = w * 16 + (lane & 15);
    const int acolbase = ((lane >> 4) & 1) * 8;
    const int brow = (lane & 7) + ((lane >> 4) & 1) * 8;
    const int bcolbase = ((lane >> 3) & 1) * 8;

    int buf = 0;
    for (int c = 0; c < 8; c++) {
        float4 xr[8];
        if (c < 7) {
            g1_ldg_x(x, xr, rowBase, c + 1, tid);
            g1_cpasync_w(wh, wl, sb, c + 1, buf ^ 1, tid);
        }

        const uint32_t aH = sb + (uint32_t)A_OFF(buf, 0);
        const uint32_t aL = sb + (uint32_t)A_OFF(buf, 1);
        const uint32_t bH = sb + (uint32_t)B_OFF(buf, 0);
        const uint32_t bL = sb + (uint32_t)B_OFF(buf, 1);

#pragma unroll
        for (int t = 0; t < 4; t++) {
            int kk = t * 16;
            uint32_t ahr[4], alr[4];
            uint32_t aoff = (uint32_t)((arow * 72 + kk + acolbase) * 2);
            ldm_x4(ahr[0], ahr[1], ahr[2], ahr[3], aH + aoff);
            ldm_x4(alr[0], alr[1], alr[2], alr[3], aL + aoff);
#pragma unroll
            for (int p = 0; p < 4; p++) {
                int n0 = p * 16;
                uint32_t boff = (uint32_t)((((n0 + brow) * 72) + kk + bcolbase) * 2);
                uint32_t bh0, bh1, bh2, bh3, bl0, bl1, bl2, bl3;
                ldm_x4(bh0, bh1, bh2, bh3, bH + boff);
                ldm_x4(bl0, bl1, bl2, bl3, bL + boff);
                mma16816(acc[2 * p],     ahr, bh0, bh1);
                mma16816(acc[2 * p],     ahr, bl0, bl1);
                mma16816(acc[2 * p],     alr, bh0, bh1);
                mma16816(acc[2 * p + 1], ahr, bh2, bh3);
                mma16816(acc[2 * p + 1], ahr, bl2, bl3);
                mma16816(acc[2 * p + 1], alr, bh2, bh3);
            }
        }

        if (c < 7) {
            g1_cvt_store(xr, smem, buf ^ 1, tid);
            asm volatile("cp.async.wait_group 0;" ::: "memory");
        }
        __syncthreads();
        buf ^= 1;
    }

    const int r0 = rowBase + w * 16 + (lane >> 2);
    const int cb = (lane & 3) * 2;
#pragma unroll
    for (int s = 0; s < 8; s++) {
        int col = s * 8 + cb;
        if (r0 < N_NODES)
            *(float2*)(g_h1 + (size_t)r0 * HIDDEN + col) = make_float2(acc[s][0], acc[s][1]);
        if (r0 + 8 < N_NODES)
            *(float2*)(g_h1 + (size_t)(r0 + 8) * HIDDEN + col) = make_float2(acc[s][2], acc[s][3]);
    }
}

// ------- layer-1 aggregation: WARP-PER-NODE (32 lanes x float2) -------------
__global__ void __launch_bounds__(256) k_agg1_gather(const float* __restrict__ h1,
                                                     const float* __restrict__ b1,
                                                     float* __restrict__ out1) {
    const int w    = threadIdx.x >> 5;
    const int lane = threadIdx.x & 31;
    const int n    = blockIdx.x * 8 + w;   // N_NODES % 8 == 0

    const float dn = g_dinv[n];
    const int start = g_rowptr[n];
    const int end   = start + g_deg[n];

    float2 v = *(const float2*)(h1 + (size_t)n * HIDDEN + lane * 2);
    float s = dn * dn;
    float2 acc = make_float2(v.x * s, v.y * s);

    int e = start;
    for (; e + 4 <= end; e += 4) {
        int s0 = g_srcs[e], s1 = g_srcs[e + 1], s2 = g_srcs[e + 2], s3 = g_srcs[e + 3];
        float w0 = g_dinv[s0] * dn, w1 = g_dinv[s1] * dn;
        float w2 = g_dinv[s2] * dn, w3 = g_dinv[s3] * dn;
        float2 m0 = *(const float2*)(h1 + (size_t)s0 * HIDDEN + lane * 2);
        float2 m1 = *(const float2*)(h1 + (size_t)s1 * HIDDEN + lane * 2);
        float2 m2 = *(const float2*)(h1 + (size_t)s2 * HIDDEN + lane * 2);
        float2 m3 = *(const float2*)(h1 + (size_t)s3 * HIDDEN + lane * 2);
        acc.x += m0.x * w0 + m1.x * w1 + m2.x * w2 + m3.x * w3;
        acc.y += m0.y * w0 + m1.y * w1 + m2.y * w2 + m3.y * w3;
    }
    for (; e < end; e++) {
        int src = g_srcs[e];
        float ww = g_dinv[src] * dn;
        float2 m = *(const float2*)(h1 + (size_t)src * HIDDEN + lane * 2);
        acc.x += m.x * ww; acc.y += m.y * ww;
    }
    float2 bb = *(const float2*)(b1 + lane * 2);
    acc.x = fmaxf(acc.x + bb.x, 0.f);
    acc.y = fmaxf(acc.y + bb.y, 0.f);
    *(float2*)(out1 + (size_t)n * HIDDEN + lane * 2) = acc;
}

// ---------------- GEMM2 (R9 version) ----------------
__global__ void __launch_bounds__(256) k_gemm2(const float* __restrict__ h1r,
                                               float* __restrict__ h2) {
    __shared__ float xs[128][65];
    __shared__ float wsT[HIDDEN * N_CLS];
    const int tid = threadIdx.x;
    const int r = tid & 127;
    const int q = tid >> 7;
    const int rowBase = blockIdx.x * 128;

#pragma unroll
    for (int m = 0; m < 8; m++) {
        int idx4 = tid + m * 256;
        int row = idx4 >> 4, kq = (idx4 & 15) * 4;
        int grow = rowBase + row;
        float4 v = make_float4(0.f, 0.f, 0.f, 0.f);
        if (grow < N_NODES)
            v = *(const float4*)(h1r + (size_t)grow * HIDDEN + kq);
        xs[row][kq + 0] = v.x; xs[row][kq + 1] = v.y;
        xs[row][kq + 2] = v.z; xs[row][kq + 3] = v.w;
    }
    for (int idx4 = tid; idx4 < 640; idx4 += 256)
        ((float4*)wsT)[idx4] = ((const float4*)g_w2t)[idx4];
    __syncthreads();

    unsigned long long acc[10];
#pragma unroll
    for (int i = 0; i < 10; i++) acc[i] = 0ull;

#pragma unroll 4
    for (int k = 0; k < HIDDEN; k++) {
        float xv = xs[r][k];
        unsigned long long xx;
        asm("mov.b64 %0, {%1, %1};" : "=l"(xx) : "f"(xv));
        const unsigned long long* wrow =
            (const unsigned long long*)(wsT + k * N_CLS + q * 20);
#pragma unroll
        for (int c = 0; c < 10; c++) {
            unsigned long long w2 = wrow[c];
            asm("fma.rn.f32x2 %0, %1, %2, %0;" : "+l"(acc[c]) : "l"(w2), "l"(xx));
        }
    }

    int grow = rowBase + r;
    if (grow < N_NODES) {
        float* dst = h2 + (size_t)grow * N_CLS + q * 20;
#pragma unroll
        for (int c = 0; c < 10; c++) {
            float a0, a1;
            asm("mov.b64 {%0,%1}, %2;" : "=f"(a0), "=f"(a1) : "l"(acc[c]));
            *(float2*)(dst + c * 2) = make_float2(a0, a1);
        }
    }
}

// ------- layer-2 aggregation: WARP-PER-NODE (20 lanes x float2) -------------
__global__ void __launch_bounds__(256) k_agg2_gather(const float* __restrict__ h2,
                                                     const float* __restrict__ b2,
                                                     float* __restrict__ out) {
    const int w    = threadIdx.x >> 5;
    const int lane = threadIdx.x & 31;
    const int n    = blockIdx.x * 8 + w;   // N_NODES % 8 == 0

    const float dn = g_dinv[n];
    const int start = g_rowptr[n];
    const int end   = start + g_deg[n];
    const bool act  = lane < 20;

    float2 acc = make_float2(0.f, 0.f);
    if (act) {
        float2 v = *(const float2*)(h2 + (size_t)n * N_CLS + lane * 2);
        float s = dn * dn;
        acc = make_float2(v.x * s, v.y * s);
    }

    int e = start;
    for (; e + 4 <= end; e += 4) {
        int s0 = g_srcs[e], s1 = g_srcs[e + 1], s2 = g_srcs[e + 2], s3 = g_srcs[e + 3];
        float w0 = g_dinv[s0] * dn, w1 = g_dinv[s1] * dn;
        float w2 = g_dinv[s2] * dn, w3 = g_dinv[s3] * dn;
        if (act) {
            float2 m0 = *(const float2*)(h2 + (size_t)s0 * N_CLS + lane * 2);
            float2 m1 = *(const float2*)(h2 + (size_t)s1 * N_CLS + lane * 2);
            float2 m2 = *(const float2*)(h2 + (size_t)s2 * N_CLS + lane * 2);
            float2 m3 = *(const float2*)(h2 + (size_t)s3 * N_CLS + lane * 2);
            acc.x += m0.x * w0 + m1.x * w1 + m2.x * w2 + m3.x * w3;
            acc.y += m0.y * w0 + m1.y * w1 + m2.y * w2 + m3.y * w3;
        }
    }
    for (; e < end; e++) {
        int src = g_srcs[e];
        float ww = g_dinv[src] * dn;
        if (act) {
            float2 m = *(const float2*)(h2 + (size_t)src * N_CLS + lane * 2);
            acc.x += m.x * ww; acc.y += m.y * ww;
        }
    }
    if (act) {
        float2 bb = *(const float2*)(b2 + lane * 2);
        acc.x += bb.x; acc.y += bb.y;
        *(float2*)(out + (size_t)n * N_CLS + lane * 2) = acc;
    }
}

// ---------------- launch ----------------
extern "C" void kernel_launch(void* const* d_in, const int* in_sizes, int n_in,
                              void* d_out, int out_size) {
    const float* x  = (const float*)d_in[0];
    const int*   ei = (const int*)d_in[1];
    const float* W1 = (const float*)d_in[2];
    const float* b1 = (const float*)d_in[3];
    const float* W2 = (const float*)d_in[4];
    const float* b2 = (const float*)d_in[5];
    float* out = (float*)d_out;

    float *h1, *out1, *h2;
    __nv_bfloat16 *wh, *wl;
    cudaGetSymbolAddress((void**)&h1,   g_h1);
    cudaGetSymbolAddress((void**)&out1, g_out1);
    cudaGetSymbolAddress((void**)&h2,   g_h2);
    cudaGetSymbolAddress((void**)&wh,   g_w1hi);
    cudaGetSymbolAddress((void**)&wl,   g_w1lo);

    k_prep<<<(N_NODES + 255) / 256, 256>>>(W1, W2);

    k_deg_count<<<(N_EDGES / 4 + 255) / 256, 256>>>(ei);
    k_scan1<<<NBLK, SCAN_B>>>();
    k_scan3<<<NBLK, SCAN_B>>>();
    k_csr_scatter<<<(N_EDGES / 4 + 255) / 256, 256>>>(ei);

    cudaFuncSetAttribute(k_gemm1_mma, cudaFuncAttributeMaxDynamicSharedMemorySize,
                         GEMM1_SMEM);
    k_gemm1_mma<<<(N_NODES + 127) / 128, 256, GEMM1_SMEM>>>(x, wh, wl);
    k_agg1_gather<<<N_NODES / 8, 256>>>(h1, b1, out1);

    k_gemm2<<<(N_NODES + 127) / 128, 256>>>(out1, h2);
    k_agg2_gather<<<N_NODES / 8, 256>>>(h2, b2, out);
}

// round 13
// speedup vs baseline: 1.0889x; 1.0539x over previous
#include <cuda_runtime.h>
#include <cuda_bf16.h>
#include <cstdint>

#define N_NODES 100000
#define N_FEATS 512
#define HIDDEN  64
#define N_CLS   40
#define N_EDGES 1600000
#define SCAN_B  1024
#define NBLK    ((N_NODES + SCAN_B - 1) / SCAN_B)   // 98

// ---------------- scratch ----------------
__device__ float g_dinv[N_NODES];
__device__ float g_h1[(size_t)N_NODES * HIDDEN];
__device__ float g_out1[(size_t)N_NODES * HIDDEN];
__device__ float g_h2[(size_t)N_NODES * N_CLS];
__device__ float g_w2t[HIDDEN * N_CLS];            // [64][40]
__device__ __nv_bfloat16 g_w1hi[HIDDEN * N_FEATS];
__device__ __nv_bfloat16 g_w1lo[HIDDEN * N_FEATS];
__device__ int   g_deg[N_NODES];
__device__ int   g_rowptr[N_NODES];
__device__ int   g_cursor[N_NODES];
__device__ int   g_srcs[N_EDGES];
__device__ int   g_bsum[NBLK];

// ---------------- helpers ----------------
__device__ __forceinline__ uint32_t smem_u32(const void* p) {
    uint32_t a;
    asm("{ .reg .u64 t; cvta.to.shared.u64 t, %1; cvt.u32.u64 %0, t; }" : "=r"(a) : "l"(p));
    return a;
}
__device__ __forceinline__ void ldm_x4(uint32_t& r0, uint32_t& r1, uint32_t& r2,
                                       uint32_t& r3, uint32_t addr) {
    asm volatile("ldmatrix.sync.aligned.m8n8.x4.shared.b16 {%0,%1,%2,%3}, [%4];"
                 : "=r"(r0), "=r"(r1), "=r"(r2), "=r"(r3) : "r"(addr));
}
__device__ __forceinline__ void mma16816(float* d, const uint32_t* a,
                                         uint32_t b0, uint32_t b1) {
    asm volatile(
        "mma.sync.aligned.m16n8k16.row.col.f32.bf16.bf16.f32 "
        "{%0,%1,%2,%3}, {%4,%5,%6,%7}, {%8,%9}, {%0,%1,%2,%3};"
        : "+f"(d[0]), "+f"(d[1]), "+f"(d[2]), "+f"(d[3])
        : "r"(a[0]), "r"(a[1]), "r"(a[2]), "r"(a[3]), "r"(b0), "r"(b1));
}
__device__ __forceinline__ void cp16(uint32_t dst, const void* src) {
    asm volatile("cp.async.cg.shared.global [%0], [%1], 16;" :: "r"(dst), "l"(src));
}

// ---------------- fused prep ----------------
__global__ void k_prep(const float* __restrict__ W1, const float* __restrict__ W2) {
    int i = blockIdx.x * blockDim.x + threadIdx.x;
    if (i < HIDDEN * N_FEATS) {
        float v = W1[i];
        __nv_bfloat16 h = __float2bfloat16(v);
        g_w1hi[i] = h;
        g_w1lo[i] = __float2bfloat16(v - __bfloat162float(h));
    }
    if (i < HIDDEN * N_CLS) {
        int k = i / N_CLS, j = i - k * N_CLS;
        g_w2t[i] = W2[j * HIDDEN + k];
    }
    if (i < N_NODES) g_deg[i] = 0;
}

// ---------------- CSR build ----------------
__global__ void k_deg_count(const int* __restrict__ ei) {
    int e = (blockIdx.x * blockDim.x + threadIdx.x) * 4;
    if (e >= N_EDGES) return;
    int4 d = *(const int4*)(ei + N_EDGES + e);
    atomicAdd(&g_deg[d.x], 1);
    atomicAdd(&g_deg[d.y], 1);
    atomicAdd(&g_deg[d.z], 1);
    atomicAdd(&g_deg[d.w], 1);
}
__global__ void __launch_bounds__(SCAN_B) k_scan1() {
    int i = blockIdx.x * SCAN_B + threadIdx.x;
    int lane = threadIdx.x & 31, wid = threadIdx.x >> 5;
    int v = (i < N_NODES) ? g_deg[i] : 0;
#pragma unroll
    for (int o = 16; o > 0; o >>= 1) v += __shfl_down_sync(0xffffffffu, v, o);
    __shared__ int ws[32];
    if (lane == 0) ws[wid] = v;
    __syncthreads();
    if (wid == 0) {
        int t = ws[lane];
#pragma unroll
        for (int o = 16; o > 0; o >>= 1) t += __shfl_down_sync(0xffffffffu, t, o);
        if (lane == 0) g_bsum[blockIdx.x] = t;
    }
}
__global__ void __launch_bounds__(SCAN_B) k_scan3() {
    const int tid = threadIdx.x;
    const int lane = tid & 31, wid = tid >> 5;
    __shared__ int ws[32];
    __shared__ int s_boff;

    int bv = (tid < blockIdx.x && tid < NBLK) ? g_bsum[tid] : 0;
#pragma unroll
    for (int o = 16; o > 0; o >>= 1) bv += __shfl_down_sync(0xffffffffu, bv, o);
    if (lane == 0) ws[wid] = bv;
    __syncthreads();
    if (wid == 0) {
        int t = ws[lane];
#pragma unroll
        for (int o = 16; o > 0; o >>= 1) t += __shfl_down_sync(0xffffffffu, t, o);
        if (lane == 0) s_boff = t;
    }
    __syncthreads();

    int i = blockIdx.x * SCAN_B + tid;
    int d = (i < N_NODES) ? g_deg[i] : 0;
    int v = d;
#pragma unroll
    for (int o = 1; o < 32; o <<= 1) {
        int n = __shfl_up_sync(0xffffffffu, v, o);
        if (lane >= o) v += n;
    }
    __syncthreads();
    if (lane == 31) ws[wid] = v;
    __syncthreads();
    if (wid == 0) {
        int t = ws[lane];
#pragma unroll
        for (int o = 1; o < 32; o <<= 1) {
            int n = __shfl_up_sync(0xffffffffu, t, o);
            if (lane >= o) t += n;
        }
        ws[lane] = t;
    }
    __syncthreads();
    int excl = s_boff + ((wid > 0) ? ws[wid - 1] : 0) + (v - d);
    if (i < N_NODES) {
        g_rowptr[i] = excl;
        g_cursor[i] = excl;
        g_dinv[i]   = rsqrtf((float)d + 1.0f);
    }
}
__global__ void k_csr_scatter(const int* __restrict__ ei) {
    int e = (blockIdx.x * blockDim.x + threadIdx.x) * 4;
    if (e >= N_EDGES) return;
    int4 s = *(const int4*)(ei + e);
    int4 d = *(const int4*)(ei + N_EDGES + e);
    int p0 = atomicAdd(&g_cursor[d.x], 1); g_srcs[p0] = s.x;
    int p1 = atomicAdd(&g_cursor[d.y], 1); g_srcs[p1] = s.y;
    int p2 = atomicAdd(&g_cursor[d.z], 1); g_srcs[p2] = s.z;
    int p3 = atomicAdd(&g_cursor[d.w], 1); g_srcs[p3] = s.w;
}

// ---------------- GEMM1: pipelined bf16 split MMA (R9 champion) -------------
#define A_OFF(buf, sp) ((size_t)((buf) * 2 + (sp)) * 18432)
#define B_OFF(buf, sp) (73728 + (size_t)((buf) * 2 + (sp)) * 9216)
#define GEMM1_SMEM (73728 + 4 * 9216)   // 110592 B

__device__ __forceinline__ void g1_cvt_store(const float4* xr, char* smem, int buf,
                                             int tid) {
    char* ah = smem + A_OFF(buf, 0);
    char* al = smem + A_OFF(buf, 1);
#pragma unroll
    for (int i = 0; i < 8; i++) {
        int idx = tid + i * 256;
        int row = idx >> 4;
        int kq  = (idx & 15) * 4;
        float4 v = xr[i];
        __nv_bfloat16 h0 = __float2bfloat16(v.x), h1 = __float2bfloat16(v.y);
        __nv_bfloat16 h2 = __float2bfloat16(v.z), h3 = __float2bfloat16(v.w);
        __nv_bfloat16 l0 = __float2bfloat16(v.x - __bfloat162float(h0));
        __nv_bfloat16 l1 = __float2bfloat16(v.y - __bfloat162float(h1));
        __nv_bfloat16 l2 = __float2bfloat16(v.z - __bfloat162float(h2));
        __nv_bfloat16 l3 = __float2bfloat16(v.w - __bfloat162float(h3));
        __nv_bfloat162 hp0 = __halves2bfloat162(h0, h1), hp1 = __halves2bfloat162(h2, h3);
        __nv_bfloat162 lp0 = __halves2bfloat162(l0, l1), lp1 = __halves2bfloat162(l2, l3);
        uint2 hv = make_uint2(*(uint32_t*)&hp0, *(uint32_t*)&hp1);
        uint2 lv = make_uint2(*(uint32_t*)&lp0, *(uint32_t*)&lp1);
        size_t off = ((size_t)row * 72 + kq) * 2;
        *(uint2*)(ah + off) = hv;
        *(uint2*)(al + off) = lv;
    }
}

__device__ __forceinline__ void g1_ldg_x(const float* __restrict__ x, float4* xr,
                                         int rowBase, int c, int tid) {
#pragma unroll
    for (int i = 0; i < 8; i++) {
        int idx = tid + i * 256;
        int row = idx >> 4;
        int kq  = (idx & 15) * 4;
        int grow = rowBase + row;
        xr[i] = make_float4(0.f, 0.f, 0.f, 0.f);
        if (grow < N_NODES)
            xr[i] = *(const float4*)(x + (size_t)grow * N_FEATS + c * 64 + kq);
    }
}

__device__ __forceinline__ void g1_cpasync_w(const __nv_bfloat16* __restrict__ wh,
                                             const __nv_bfloat16* __restrict__ wl,
                                             uint32_t sb, int c, int buf, int tid) {
#pragma unroll
    for (int i = 0; i < 2; i++) {
        int idx = tid + i * 256;
        int n = idx >> 3, j = idx & 7;
        uint32_t off = (uint32_t)(((size_t)n * 72 + j * 8) * 2);
        cp16(sb + (uint32_t)B_OFF(buf, 0) + off, wh + (size_t)n * N_FEATS + c * 64 + j * 8);
        cp16(sb + (uint32_t)B_OFF(buf, 1) + off, wl + (size_t)n * N_FEATS + c * 64 + j * 8);
    }
    asm volatile("cp.async.commit_group;" ::: "memory");
}

__global__ void __launch_bounds__(256) k_gemm1_mma(const float* __restrict__ x,
                                                   const __nv_bfloat16* __restrict__ wh,
                                                   const __nv_bfloat16* __restrict__ wl) {
    extern __shared__ __align__(16) char smem[];
    const uint32_t sb = smem_u32(smem);
    const int tid = threadIdx.x, w = tid >> 5, lane = tid & 31;
    const int rowBase = blockIdx.x * 128;

    float acc[8][4];
#pragma unroll
    for (int s = 0; s < 8; s++)
#pragma unroll
        for (int j = 0; j < 4; j++) acc[s][j] = 0.f;

    {
        float4 xr[8];
        g1_ldg_x(x, xr, rowBase, 0, tid);
        g1_cpasync_w(wh, wl, sb, 0, 0, tid);
        g1_cvt_store(xr, smem, 0, tid);
        asm volatile("cp.async.wait_group 0;" ::: "memory");
    }
    __syncthreads();

    const int arow = w * 16 + (lane & 15);
    const int acolbase = ((lane >> 4) & 1) * 8;
    const int brow = (lane & 7) + ((lane >> 4) & 1) * 8;
    const int bcolbase = ((lane >> 3) & 1) * 8;

    int buf = 0;
    for (int c = 0; c < 8; c++) {
        float4 xr[8];
        if (c < 7) {
            g1_ldg_x(x, xr, rowBase, c + 1, tid);
            g1_cpasync_w(wh, wl, sb, c + 1, buf ^ 1, tid);
        }

        const uint32_t aH = sb + (uint32_t)A_OFF(buf, 0);
        const uint32_t aL = sb + (uint32_t)A_OFF(buf, 1);
        const uint32_t bH = sb + (uint32_t)B_OFF(buf, 0);
        const uint32_t bL = sb + (uint32_t)B_OFF(buf, 1);

#pragma unroll
        for (int t = 0; t < 4; t++) {
            int kk = t * 16;
            uint32_t ahr[4], alr[4];
            uint32_t aoff = (uint32_t)((arow * 72 + kk + acolbase) * 2);
            ldm_x4(ahr[0], ahr[1], ahr[2], ahr[3], aH + aoff);
            ldm_x4(alr[0], alr[1], alr[2], alr[3], aL + aoff);
#pragma unroll
            for (int p = 0; p < 4; p++) {
                int n0 = p * 16;
                uint32_t boff = (uint32_t)((((n0 + brow) * 72) + kk + bcolbase) * 2);
                uint32_t bh0, bh1, bh2, bh3, bl0, bl1, bl2, bl3;
                ldm_x4(bh0, bh1, bh2, bh3, bH + boff);
                ldm_x4(bl0, bl1, bl2, bl3, bL + boff);
                mma16816(acc[2 * p],     ahr, bh0, bh1);
                mma16816(acc[2 * p],     ahr, bl0, bl1);
                mma16816(acc[2 * p],     alr, bh0, bh1);
                mma16816(acc[2 * p + 1], ahr, bh2, bh3);
                mma16816(acc[2 * p + 1], ahr, bl2, bl3);
                mma16816(acc[2 * p + 1], alr, bh2, bh3);
            }
        }

        if (c < 7) {
            g1_cvt_store(xr, smem, buf ^ 1, tid);
            asm volatile("cp.async.wait_group 0;" ::: "memory");
        }
        __syncthreads();
        buf ^= 1;
    }

    const int r0 = rowBase + w * 16 + (lane >> 2);
    const int cb = (lane & 3) * 2;
#pragma unroll
    for (int s = 0; s < 8; s++) {
        int col = s * 8 + cb;
        if (r0 < N_NODES)
            *(float2*)(g_h1 + (size_t)r0 * HIDDEN + col) = make_float2(acc[s][0], acc[s][1]);
        if (r0 + 8 < N_NODES)
            *(float2*)(g_h1 + (size_t)(r0 + 8) * HIDDEN + col) = make_float2(acc[s][2], acc[s][3]);
    }
}

// ---------------- layer-1 aggregation (R9/R6 16-lane float4 form) -----------
__global__ void __launch_bounds__(256) k_agg1_gather(const float* __restrict__ h1,
                                                     const float* __restrict__ b1,
                                                     float* __restrict__ out1) {
    const int tid  = threadIdx.x;
    const int g    = tid >> 4;
    const int lane = tid & 15;
    const int n    = blockIdx.x * 16 + g;
    if (n >= N_NODES) return;

    const float dn = g_dinv[n];
    const int start = g_rowptr[n];
    const int end   = start + g_deg[n];

    float4 v = *(const float4*)(h1 + (size_t)n * HIDDEN + lane * 4);
    float s = dn * dn;
    float4 acc = make_float4(v.x * s, v.y * s, v.z * s, v.w * s);

    int e = start;
    for (; e + 4 <= end; e += 4) {
        int s0 = g_srcs[e], s1 = g_srcs[e + 1], s2 = g_srcs[e + 2], s3 = g_srcs[e + 3];
        float w0 = g_dinv[s0] * dn, w1 = g_dinv[s1] * dn;
        float w2 = g_dinv[s2] * dn, w3 = g_dinv[s3] * dn;
        float4 m0 = *(const float4*)(h1 + (size_t)s0 * HIDDEN + lane * 4);
        float4 m1 = *(const float4*)(h1 + (size_t)s1 * HIDDEN + lane * 4);
        float4 m2 = *(const float4*)(h1 + (size_t)s2 * HIDDEN + lane * 4);
        float4 m3 = *(const float4*)(h1 + (size_t)s3 * HIDDEN + lane * 4);
        acc.x += m0.x * w0 + m1.x * w1 + m2.x * w2 + m3.x * w3;
        acc.y += m0.y * w0 + m1.y * w1 + m2.y * w2 + m3.y * w3;
        acc.z += m0.z * w0 + m1.z * w1 + m2.z * w2 + m3.z * w3;
        acc.w += m0.w * w0 + m1.w * w1 + m2.w * w2 + m3.w * w3;
    }
    for (; e < end; e++) {
        int src = g_srcs[e];
        float w = g_dinv[src] * dn;
        float4 m = *(const float4*)(h1 + (size_t)src * HIDDEN + lane * 4);
        acc.x += m.x * w; acc.y += m.y * w; acc.z += m.z * w; acc.w += m.w * w;
    }
    float4 bb = *(const float4*)(b1 + lane * 4);
    acc.x = fmaxf(acc.x + bb.x, 0.f);
    acc.y = fmaxf(acc.y + bb.y, 0.f);
    acc.z = fmaxf(acc.z + bb.z, 0.f);
    acc.w = fmaxf(acc.w + bb.w, 0.f);
    *(float4*)(out1 + (size_t)n * HIDDEN + lane * 4) = acc;
}

// ---------------- GEMM2 (R9 version) ----------------
__global__ void __launch_bounds__(256) k_gemm2(const float* __restrict__ h1r,
                                               float* __restrict__ h2) {
    __shared__ float xs[128][65];
    __shared__ float wsT[HIDDEN * N_CLS];
    const int tid = threadIdx.x;
    const int r = tid & 127;
    const int q = tid >> 7;
    const int rowBase = blockIdx.x * 128;

#pragma unroll
    for (int m = 0; m < 8; m++) {
        int idx4 = tid + m * 256;
        int row = idx4 >> 4, kq = (idx4 & 15) * 4;
        int grow = rowBase + row;
        float4 v = make_float4(0.f, 0.f, 0.f, 0.f);
        if (grow < N_NODES)
            v = *(const float4*)(h1r + (size_t)grow * HIDDEN + kq);
        xs[row][kq + 0] = v.x; xs[row][kq + 1] = v.y;
        xs[row][kq + 2] = v.z; xs[row][kq + 3] = v.w;
    }
    for (int idx4 = tid; idx4 < 640; idx4 += 256)
        ((float4*)wsT)[idx4] = ((const float4*)g_w2t)[idx4];
    __syncthreads();

    unsigned long long acc[10];
#pragma unroll
    for (int i = 0; i < 10; i++) acc[i] = 0ull;

#pragma unroll 4
    for (int k = 0; k < HIDDEN; k++) {
        float xv = xs[r][k];
        unsigned long long xx;
        asm("mov.b64 %0, {%1, %1};" : "=l"(xx) : "f"(xv));
        const unsigned long long* wrow =
            (const unsigned long long*)(wsT + k * N_CLS + q * 20);
#pragma unroll
        for (int c = 0; c < 10; c++) {
            unsigned long long w2 = wrow[c];
            asm("fma.rn.f32x2 %0, %1, %2, %0;" : "+l"(acc[c]) : "l"(w2), "l"(xx));
        }
    }

    int grow = rowBase + r;
    if (grow < N_NODES) {
        float* dst = h2 + (size_t)grow * N_CLS + q * 20;
#pragma unroll
        for (int c = 0; c < 10; c++) {
            float a0, a1;
            asm("mov.b64 {%0,%1}, %2;" : "=f"(a0), "=f"(a1) : "l"(acc[c]));
            *(float2*)(dst + c * 2) = make_float2(a0, a1);
        }
    }
}

// ---------------- layer-2 aggregation (R9/R6 form) ----------------
__global__ void __launch_bounds__(256) k_agg2_gather(const float* __restrict__ h2,
                                                     const float* __restrict__ b2,
                                                     float* __restrict__ out) {
    const int tid  = threadIdx.x;
    const int g    = tid >> 4;
    const int lane = tid & 15;
    const int n    = blockIdx.x * 16 + g;
    if (n >= N_NODES || lane >= 10) return;

    const float dn = g_dinv[n];
    const int start = g_rowptr[n];
    const int end   = start + g_deg[n];

    float4 v = *(const float4*)(h2 + (size_t)n * N_CLS + lane * 4);
    float s = dn * dn;
    float4 acc = make_float4(v.x * s, v.y * s, v.z * s, v.w * s);

    int e = start;
    for (; e + 4 <= end; e += 4) {
        int s0 = g_srcs[e], s1 = g_srcs[e + 1], s2 = g_srcs[e + 2], s3 = g_srcs[e + 3];
        float w0 = g_dinv[s0] * dn, w1 = g_dinv[s1] * dn;
        float w2 = g_dinv[s2] * dn, w3 = g_dinv[s3] * dn;
        float4 m0 = *(const float4*)(h2 + (size_t)s0 * N_CLS + lane * 4);
        float4 m1 = *(const float4*)(h2 + (size_t)s1 * N_CLS + lane * 4);
        float4 m2 = *(const float4*)(h2 + (size_t)s2 * N_CLS + lane * 4);
        float4 m3 = *(const float4*)(h2 + (size_t)s3 * N_CLS + lane * 4);
        acc.x += m0.x * w0 + m1.x * w1 + m2.x * w2 + m3.x * w3;
        acc.y += m0.y * w0 + m1.y * w1 + m2.y * w2 + m3.y * w3;
        acc.z += m0.z * w0 + m1.z * w1 + m2.z * w2 + m3.z * w3;
        acc.w += m0.w * w0 + m1.w * w1 + m2.w * w2 + m3.w * w3;
    }
    for (; e < end; e++) {
        int src = g_srcs[e];
        float w = g_dinv[src] * dn;
        float4 m = *(const float4*)(h2 + (size_t)src * N_CLS + lane * 4);
        acc.x += m.x * w; acc.y += m.y * w; acc.z += m.z * w; acc.w += m.w * w;
    }
    float4 bb = *(const float4*)(b2 + lane * 4);
    acc.x += bb.x; acc.y += bb.y; acc.z += bb.z; acc.w += bb.w;
    *(float4*)(out + (size_t)n * N_CLS + lane * 4) = acc;
}

// ---------------- launch ----------------
extern "C" void kernel_launch(void* const* d_in, const int* in_sizes, int n_in,
                              void* d_out, int out_size) {
    const float* x  = (const float*)d_in[0];
    const int*   ei = (const int*)d_in[1];
    const float* W1 = (const float*)d_in[2];
    const float* b1 = (const float*)d_in[3];
    const float* W2 = (const float*)d_in[4];
    const float* b2 = (const float*)d_in[5];
    float* out = (float*)d_out;

    float *h1, *out1, *h2;
    __nv_bfloat16 *wh, *wl;
    cudaGetSymbolAddress((void**)&h1,   g_h1);
    cudaGetSymbolAddress((void**)&out1, g_out1);
    cudaGetSymbolAddress((void**)&h2,   g_h2);
    cudaGetSymbolAddress((void**)&wh,   g_w1hi);
    cudaGetSymbolAddress((void**)&wl,   g_w1lo);

    static bool attrSet = false;
    if (!attrSet) {
        cudaFuncSetAttribute(k_gemm1_mma, cudaFuncAttributeMaxDynamicSharedMemorySize,
                             GEMM1_SMEM);
        // request max smem carveout so 2 CTAs (2x110592B = 221184B) can co-reside
        cudaFuncSetAttribute(k_gemm1_mma, cudaFuncAttributePreferredSharedMemoryCarveout,
                             100);
        attrSet = true;
    }

    k_prep<<<(N_NODES + 255) / 256, 256>>>(W1, W2);

    k_deg_count<<<(N_EDGES / 4 + 255) / 256, 256>>>(ei);
    k_scan1<<<NBLK, SCAN_B>>>();
    k_scan3<<<NBLK, SCAN_B>>>();
    k_csr_scatter<<<(N_EDGES / 4 + 255) / 256, 256>>>(ei);

    k_gemm1_mma<<<(N_NODES + 127) / 128, 256, GEMM1_SMEM>>>(x, wh, wl);
    k_agg1_gather<<<(N_NODES + 15) / 16, 256>>>(h1, b1, out1);

    k_gemm2<<<(N_NODES + 127) / 128, 256>>>(out1, h2);
    k_agg2_gather<<<(N_NODES + 15) / 16, 256>>>(h2, b2, out);
}

// round 14
// speedup vs baseline: 1.1519x; 1.0578x over previous
#include <cuda_runtime.h>
#include <cuda_bf16.h>
#include <cuda_fp16.h>
#include <cstdint>

#define N_NODES 100000
#define N_FEATS 512
#define HIDDEN  64
#define N_CLS   40
#define N_EDGES 1600000
#define SCAN_B  1024
#define NBLK    ((N_NODES + SCAN_B - 1) / SCAN_B)   // 98

// ---------------- scratch ----------------
__device__ float  g_dinv[N_NODES];
__device__ __half g_h1h[(size_t)N_NODES * HIDDEN];   // fp16 hidden (layer 1)
__device__ float  g_out1[(size_t)N_NODES * HIDDEN];
__device__ __half g_h2h[(size_t)N_NODES * N_CLS];    // fp16 hidden (layer 2)
__device__ float  g_w2t[HIDDEN * N_CLS];             // [64][40]
__device__ __nv_bfloat16 g_w1hi[HIDDEN * N_FEATS];
__device__ __nv_bfloat16 g_w1lo[HIDDEN * N_FEATS];
__device__ int   g_deg[N_NODES];
__device__ int   g_rowptr[N_NODES];
__device__ int   g_cursor[N_NODES];
__device__ int   g_srcs[N_EDGES];
__device__ int   g_bsum[NBLK];

// ---------------- helpers ----------------
__device__ __forceinline__ uint32_t smem_u32(const void* p) {
    uint32_t a;
    asm("{ .reg .u64 t; cvta.to.shared.u64 t, %1; cvt.u32.u64 %0, t; }" : "=r"(a) : "l"(p));
    return a;
}
__device__ __forceinline__ void ldm_x4(uint32_t& r0, uint32_t& r1, uint32_t& r2,
                                       uint32_t& r3, uint32_t addr) {
    asm volatile("ldmatrix.sync.aligned.m8n8.x4.shared.b16 {%0,%1,%2,%3}, [%4];"
                 : "=r"(r0), "=r"(r1), "=r"(r2), "=r"(r3) : "r"(addr));
}
__device__ __forceinline__ void mma16816(float* d, const uint32_t* a,
                                         uint32_t b0, uint32_t b1) {
    asm volatile(
        "mma.sync.aligned.m16n8k16.row.col.f32.bf16.bf16.f32 "
        "{%0,%1,%2,%3}, {%4,%5,%6,%7}, {%8,%9}, {%0,%1,%2,%3};"
        : "+f"(d[0]), "+f"(d[1]), "+f"(d[2]), "+f"(d[3])
        : "r"(a[0]), "r"(a[1]), "r"(a[2]), "r"(a[3]), "r"(b0), "r"(b1));
}
__device__ __forceinline__ void cp16(uint32_t dst, const void* src) {
    asm volatile("cp.async.cg.shared.global [%0], [%1], 16;" :: "r"(dst), "l"(src));
}
// accumulate a packed half2 (as uint32) into float2 acc with weight w
__device__ __forceinline__ void acc_h2(float& ax, float& ay, uint32_t h, float w) {
    float2 f = __half22float2(*(const __half2*)&h);
    ax += f.x * w; ay += f.y * w;
}

// ---------------- fused prep ----------------
__global__ void k_prep(const float* __restrict__ W1, const float* __restrict__ W2) {
    int i = blockIdx.x * blockDim.x + threadIdx.x;
    if (i < HIDDEN * N_FEATS) {
        float v = W1[i];
        __nv_bfloat16 h = __float2bfloat16(v);
        g_w1hi[i] = h;
        g_w1lo[i] = __float2bfloat16(v - __bfloat162float(h));
    }
    if (i < HIDDEN * N_CLS) {
        int k = i / N_CLS, j = i - k * N_CLS;
        g_w2t[i] = W2[j * HIDDEN + k];
    }
    if (i < N_NODES) g_deg[i] = 0;
}

// ---------------- CSR build ----------------
__global__ void k_deg_count(const int* __restrict__ ei) {
    int e = (blockIdx.x * blockDim.x + threadIdx.x) * 4;
    if (e >= N_EDGES) return;
    int4 d = *(const int4*)(ei + N_EDGES + e);
    atomicAdd(&g_deg[d.x], 1);
    atomicAdd(&g_deg[d.y], 1);
    atomicAdd(&g_deg[d.z], 1);
    atomicAdd(&g_deg[d.w], 1);
}
__global__ void __launch_bounds__(SCAN_B) k_scan1() {
    int i = blockIdx.x * SCAN_B + threadIdx.x;
    int lane = threadIdx.x & 31, wid = threadIdx.x >> 5;
    int v = (i < N_NODES) ? g_deg[i] : 0;
#pragma unroll
    for (int o = 16; o > 0; o >>= 1) v += __shfl_down_sync(0xffffffffu, v, o);
    __shared__ int ws[32];
    if (lane == 0) ws[wid] = v;
    __syncthreads();
    if (wid == 0) {
        int t = ws[lane];
#pragma unroll
        for (int o = 16; o > 0; o >>= 1) t += __shfl_down_sync(0xffffffffu, t, o);
        if (lane == 0) g_bsum[blockIdx.x] = t;
    }
}
__global__ void __launch_bounds__(SCAN_B) k_scan3() {
    const int tid = threadIdx.x;
    const int lane = tid & 31, wid = tid >> 5;
    __shared__ int ws[32];
    __shared__ int s_boff;

    int bv = (tid < blockIdx.x && tid < NBLK) ? g_bsum[tid] : 0;
#pragma unroll
    for (int o = 16; o > 0; o >>= 1) bv += __shfl_down_sync(0xffffffffu, bv, o);
    if (lane == 0) ws[wid] = bv;
    __syncthreads();
    if (wid == 0) {
        int t = ws[lane];
#pragma unroll
        for (int o = 16; o > 0; o >>= 1) t += __shfl_down_sync(0xffffffffu, t, o);
        if (lane == 0) s_boff = t;
    }
    __syncthreads();

    int i = blockIdx.x * SCAN_B + tid;
    int d = (i < N_NODES) ? g_deg[i] : 0;
    int v = d;
#pragma unroll
    for (int o = 1; o < 32; o <<= 1) {
        int n = __shfl_up_sync(0xffffffffu, v, o);
        if (lane >= o) v += n;
    }
    __syncthreads();
    if (lane == 31) ws[wid] = v;
    __syncthreads();
    if (wid == 0) {
        int t = ws[lane];
#pragma unroll
        for (int o = 1; o < 32; o <<= 1) {
            int n = __shfl_up_sync(0xffffffffu, t, o);
            if (lane >= o) t += n;
        }
        ws[lane] = t;
    }
    __syncthreads();
    int excl = s_boff + ((wid > 0) ? ws[wid - 1] : 0) + (v - d);
    if (i < N_NODES) {
        g_rowptr[i] = excl;
        g_cursor[i] = excl;
        g_dinv[i]   = rsqrtf((float)d + 1.0f);
    }
}
__global__ void k_csr_scatter(const int* __restrict__ ei) {
    int e = (blockIdx.x * blockDim.x + threadIdx.x) * 4;
    if (e >= N_EDGES) return;
    int4 s = *(const int4*)(ei + e);
    int4 d = *(const int4*)(ei + N_EDGES + e);
    int p0 = atomicAdd(&g_cursor[d.x], 1); g_srcs[p0] = s.x;
    int p1 = atomicAdd(&g_cursor[d.y], 1); g_srcs[p1] = s.y;
    int p2 = atomicAdd(&g_cursor[d.z], 1); g_srcs[p2] = s.z;
    int p3 = atomicAdd(&g_cursor[d.w], 1); g_srcs[p3] = s.w;
}

// ---------------- GEMM1: pipelined bf16 split MMA, fp16 epilogue ------------
#define A_OFF(buf, sp) ((size_t)((buf) * 2 + (sp)) * 18432)
#define B_OFF(buf, sp) (73728 + (size_t)((buf) * 2 + (sp)) * 9216)
#define GEMM1_SMEM (73728 + 4 * 9216)   // 110592 B

__device__ __forceinline__ void g1_cvt_store(const float4* xr, char* smem, int buf,
                                             int tid) {
    char* ah = smem + A_OFF(buf, 0);
    char* al = smem + A_OFF(buf, 1);
#pragma unroll
    for (int i = 0; i < 8; i++) {
        int idx = tid + i * 256;
        int row = idx >> 4;
        int kq  = (idx & 15) * 4;
        float4 v = xr[i];
        __nv_bfloat16 h0 = __float2bfloat16(v.x), h1 = __float2bfloat16(v.y);
        __nv_bfloat16 h2 = __float2bfloat16(v.z), h3 = __float2bfloat16(v.w);
        __nv_bfloat16 l0 = __float2bfloat16(v.x - __bfloat162float(h0));
        __nv_bfloat16 l1 = __float2bfloat16(v.y - __bfloat162float(h1));
        __nv_bfloat16 l2 = __float2bfloat16(v.z - __bfloat162float(h2));
        __nv_bfloat16 l3 = __float2bfloat16(v.w - __bfloat162float(h3));
        __nv_bfloat162 hp0 = __halves2bfloat162(h0, h1), hp1 = __halves2bfloat162(h2, h3);
        __nv_bfloat162 lp0 = __halves2bfloat162(l0, l1), lp1 = __halves2bfloat162(l2, l3);
        uint2 hv = make_uint2(*(uint32_t*)&hp0, *(uint32_t*)&hp1);
        uint2 lv = make_uint2(*(uint32_t*)&lp0, *(uint32_t*)&lp1);
        size_t off = ((size_t)row * 72 + kq) * 2;
        *(uint2*)(ah + off) = hv;
        *(uint2*)(al + off) = lv;
    }
}

__device__ __forceinline__ void g1_ldg_x(const float* __restrict__ x, float4* xr,
                                         int rowBase, int c, int tid) {
#pragma unroll
    for (int i = 0; i < 8; i++) {
        int idx = tid + i * 256;
        int row = idx >> 4;
        int kq  = (idx & 15) * 4;
        int grow = rowBase + row;
        xr[i] = make_float4(0.f, 0.f, 0.f, 0.f);
        if (grow < N_NODES)
            xr[i] = *(const float4*)(x + (size_t)grow * N_FEATS + c * 64 + kq);
    }
}

__device__ __forceinline__ void g1_cpasync_w(const __nv_bfloat16* __restrict__ wh,
                                             const __nv_bfloat16* __restrict__ wl,
                                             uint32_t sb, int c, int buf, int tid) {
#pragma unroll
    for (int i = 0; i < 2; i++) {
        int idx = tid + i * 256;
        int n = idx >> 3, j = idx & 7;
        uint32_t off = (uint32_t)(((size_t)n * 72 + j * 8) * 2);
        cp16(sb + (uint32_t)B_OFF(buf, 0) + off, wh + (size_t)n * N_FEATS + c * 64 + j * 8);
        cp16(sb + (uint32_t)B_OFF(buf, 1) + off, wl + (size_t)n * N_FEATS + c * 64 + j * 8);
    }
    asm volatile("cp.async.commit_group;" ::: "memory");
}

__global__ void __launch_bounds__(256) k_gemm1_mma(const float* __restrict__ x,
                                                   const __nv_bfloat16* __restrict__ wh,
                                                   const __nv_bfloat16* __restrict__ wl) {
    extern __shared__ __align__(16) char smem[];
    const uint32_t sb = smem_u32(smem);
    const int tid = threadIdx.x, w = tid >> 5, lane = tid & 31;
    const int rowBase = blockIdx.x * 128;

    float acc[8][4];
#pragma unroll
    for (int s = 0; s < 8; s++)
#pragma unroll
        for (int j = 0; j < 4; j++) acc[s][j] = 0.f;

    {
        float4 xr[8];
        g1_ldg_x(x, xr, rowBase, 0, tid);
        g1_cpasync_w(wh, wl, sb, 0, 0, tid);
        g1_cvt_store(xr, smem, 0, tid);
        asm volatile("cp.async.wait_group 0;" ::: "memory");
    }
    __syncthreads();

    const int arow = w * 16 + (lane & 15);
    const int acolbase = ((lane >> 4) & 1) * 8;
    const int brow = (lane & 7) + ((lane >> 4) & 1) * 8;
    const int bcolbase = ((lane >> 3) & 1) * 8;

    int buf = 0;
    for (int c = 0; c < 8; c++) {
        float4 xr[8];
        if (c < 7) {
            g1_ldg_x(x, xr, rowBase, c + 1, tid);
            g1_cpasync_w(wh, wl, sb, c + 1, buf ^ 1, tid);
        }

        const uint32_t aH = sb + (uint32_t)A_OFF(buf, 0);
        const uint32_t aL = sb + (uint32_t)A_OFF(buf, 1);
        const uint32_t bH = sb + (uint32_t)B_OFF(buf, 0);
        const uint32_t bL = sb + (uint32_t)B_OFF(buf, 1);

#pragma unroll
        for (int t = 0; t < 4; t++) {
            int kk = t * 16;
            uint32_t ahr[4], alr[4];
            uint32_t aoff = (uint32_t)((arow * 72 + kk + acolbase) * 2);
            ldm_x4(ahr[0], ahr[1], ahr[2], ahr[3], aH + aoff);
            ldm_x4(alr[0], alr[1], alr[2], alr[3], aL + aoff);
#pragma unroll
            for (int p = 0; p < 4; p++) {
                int n0 = p * 16;
                uint32_t boff = (uint32_t)((((n0 + brow) * 72) + kk + bcolbase) * 2);
                uint32_t bh0, bh1, bh2, bh3, bl0, bl1, bl2, bl3;
                ldm_x4(bh0, bh1, bh2, bh3, bH + boff);
                ldm_x4(bl0, bl1, bl2, bl3, bL + boff);
                mma16816(acc[2 * p],     ahr, bh0, bh1);
                mma16816(acc[2 * p],     ahr, bl0, bl1);
                mma16816(acc[2 * p],     alr, bh0, bh1);
                mma16816(acc[2 * p + 1], ahr, bh2, bh3);
                mma16816(acc[2 * p + 1], ahr, bl2, bl3);
                mma16816(acc[2 * p + 1], alr, bh2, bh3);
            }
        }

        if (c < 7) {
            g1_cvt_store(xr, smem, buf ^ 1, tid);
            asm volatile("cp.async.wait_group 0;" ::: "memory");
        }
        __syncthreads();
        buf ^= 1;
    }

    // epilogue: write h1 as fp16 (half2 per col pair)
    const int r0 = rowBase + w * 16 + (lane >> 2);
    const int cb = (lane & 3) * 2;
#pragma unroll
    for (int s = 0; s < 8; s++) {
        int col = s * 8 + cb;
        if (r0 < N_NODES) {
            __half2 h = __floats2half2_rn(acc[s][0], acc[s][1]);
            *(__half2*)(g_h1h + (size_t)r0 * HIDDEN + col) = h;
        }
        if (r0 + 8 < N_NODES) {
            __half2 h = __floats2half2_rn(acc[s][2], acc[s][3]);
            *(__half2*)(g_h1h + (size_t)(r0 + 8) * HIDDEN + col) = h;
        }
    }
}

// ------- layer-1 aggregation: 16-lane groups over fp16 rows -----------------
__global__ void __launch_bounds__(256) k_agg1_gather(const float* __restrict__ b1,
                                                     float* __restrict__ out1) {
    const int tid  = threadIdx.x;
    const int g    = tid >> 4;
    const int lane = tid & 15;
    const int n    = blockIdx.x * 16 + g;
    if (n >= N_NODES) return;

    const float dn = g_dinv[n];
    const int start = g_rowptr[n];
    const int end   = start + g_deg[n];

    uint2 qn = *(const uint2*)(g_h1h + (size_t)n * HIDDEN + lane * 4);
    float s = dn * dn;
    float ax = 0.f, ay = 0.f, az = 0.f, aw = 0.f;
    acc_h2(ax, ay, qn.x, s);
    acc_h2(az, aw, qn.y, s);

    int e = start;
    for (; e + 4 <= end; e += 4) {
        int s0 = g_srcs[e], s1 = g_srcs[e + 1], s2 = g_srcs[e + 2], s3 = g_srcs[e + 3];
        float w0 = g_dinv[s0] * dn, w1 = g_dinv[s1] * dn;
        float w2 = g_dinv[s2] * dn, w3 = g_dinv[s3] * dn;
        uint2 m0 = *(const uint2*)(g_h1h + (size_t)s0 * HIDDEN + lane * 4);
        uint2 m1 = *(const uint2*)(g_h1h + (size_t)s1 * HIDDEN + lane * 4);
        uint2 m2 = *(const uint2*)(g_h1h + (size_t)s2 * HIDDEN + lane * 4);
        uint2 m3 = *(const uint2*)(g_h1h + (size_t)s3 * HIDDEN + lane * 4);
        acc_h2(ax, ay, m0.x, w0); acc_h2(az, aw, m0.y, w0);
        acc_h2(ax, ay, m1.x, w1); acc_h2(az, aw, m1.y, w1);
        acc_h2(ax, ay, m2.x, w2); acc_h2(az, aw, m2.y, w2);
        acc_h2(ax, ay, m3.x, w3); acc_h2(az, aw, m3.y, w3);
    }
    for (; e < end; e++) {
        int src = g_srcs[e];
        float w = g_dinv[src] * dn;
        uint2 m = *(const uint2*)(g_h1h + (size_t)src * HIDDEN + lane * 4);
        acc_h2(ax, ay, m.x, w); acc_h2(az, aw, m.y, w);
    }
    float4 bb = *(const float4*)(b1 + lane * 4);
    float4 r;
    r.x = fmaxf(ax + bb.x, 0.f);
    r.y = fmaxf(ay + bb.y, 0.f);
    r.z = fmaxf(az + bb.z, 0.f);
    r.w = fmaxf(aw + bb.w, 0.f);
    *(float4*)(out1 + (size_t)n * HIDDEN + lane * 4) = r;
}

// ---------------- GEMM2: h2h[N][40] = out1[N][64] @ W2^T (fp16 out) ---------
__global__ void __launch_bounds__(256) k_gemm2(const float* __restrict__ h1r) {
    __shared__ float xs[128][65];
    __shared__ float wsT[HIDDEN * N_CLS];
    const int tid = threadIdx.x;
    const int r = tid & 127;
    const int q = tid >> 7;
    const int rowBase = blockIdx.x * 128;

#pragma unroll
    for (int m = 0; m < 8; m++) {
        int idx4 = tid + m * 256;
        int row = idx4 >> 4, kq = (idx4 & 15) * 4;
        int grow = rowBase + row;
        float4 v = make_float4(0.f, 0.f, 0.f, 0.f);
        if (grow < N_NODES)
            v = *(const float4*)(h1r + (size_t)grow * HIDDEN + kq);
        xs[row][kq + 0] = v.x; xs[row][kq + 1] = v.y;
        xs[row][kq + 2] = v.z; xs[row][kq + 3] = v.w;
    }
    for (int idx4 = tid; idx4 < 640; idx4 += 256)
        ((float4*)wsT)[idx4] = ((const float4*)g_w2t)[idx4];
    __syncthreads();

    unsigned long long acc[10];
#pragma unroll
    for (int i = 0; i < 10; i++) acc[i] = 0ull;

#pragma unroll 4
    for (int k = 0; k < HIDDEN; k++) {
        float xv = xs[r][k];
        unsigned long long xx;
        asm("mov.b64 %0, {%1, %1};" : "=l"(xx) : "f"(xv));
        const unsigned long long* wrow =
            (const unsigned long long*)(wsT + k * N_CLS + q * 20);
#pragma unroll
        for (int c = 0; c < 10; c++) {
            unsigned long long w2 = wrow[c];
            asm("fma.rn.f32x2 %0, %1, %2, %0;" : "+l"(acc[c]) : "l"(w2), "l"(xx));
        }
    }

    int grow = rowBase + r;
    if (grow < N_NODES) {
        __half* dst = g_h2h + (size_t)grow * N_CLS + q * 20;
#pragma unroll
        for (int c = 0; c < 10; c++) {
            float a0, a1;
            asm("mov.b64 {%0,%1}, %2;" : "=f"(a0), "=f"(a1) : "l"(acc[c]));
            *(__half2*)(dst + c * 2) = __floats2half2_rn(a0, a1);
        }
    }
}

// ------- layer-2 aggregation: 16-lane groups over fp16 rows -----------------
__global__ void __launch_bounds__(256) k_agg2_gather(const float* __restrict__ b2,
                                                     float* __restrict__ out) {
    const int tid  = threadIdx.x;
    const int g    = tid >> 4;
    const int lane = tid & 15;
    const int n    = blockIdx.x * 16 + g;
    if (n >= N_NODES || lane >= 10) return;

    const float dn = g_dinv[n];
    const int start = g_rowptr[n];
    const int end   = start + g_deg[n];

    uint2 qn = *(const uint2*)(g_h2h + (size_t)n * N_CLS + lane * 4);
    float s = dn * dn;
    float ax = 0.f, ay = 0.f, az = 0.f, aw = 0.f;
    acc_h2(ax, ay, qn.x, s);
    acc_h2(az, aw, qn.y, s);

    int e = start;
    for (; e + 4 <= end; e += 4) {
        int s0 = g_srcs[e], s1 = g_srcs[e + 1], s2 = g_srcs[e + 2], s3 = g_srcs[e + 3];
        float w0 = g_dinv[s0] * dn, w1 = g_dinv[s1] * dn;
        float w2 = g_dinv[s2] * dn, w3 = g_dinv[s3] * dn;
        uint2 m0 = *(const uint2*)(g_h2h + (size_t)s0 * N_CLS + lane * 4);
        uint2 m1 = *(const uint2*)(g_h2h + (size_t)s1 * N_CLS + lane * 4);
        uint2 m2 = *(const uint2*)(g_h2h + (size_t)s2 * N_CLS + lane * 4);
        uint2 m3 = *(const uint2*)(g_h2h + (size_t)s3 * N_CLS + lane * 4);
        acc_h2(ax, ay, m0.x, w0); acc_h2(az, aw, m0.y, w0);
        acc_h2(ax, ay, m1.x, w1); acc_h2(az, aw, m1.y, w1);
        acc_h2(ax, ay, m2.x, w2); acc_h2(az, aw, m2.y, w2);
        acc_h2(ax, ay, m3.x, w3); acc_h2(az, aw, m3.y, w3);
    }
    for (; e < end; e++) {
        int src = g_srcs[e];
        float w = g_dinv[src] * dn;
        uint2 m = *(const uint2*)(g_h2h + (size_t)src * N_CLS + lane * 4);
        acc_h2(ax, ay, m.x, w); acc_h2(az, aw, m.y, w);
    }
    float4 bb = *(const float4*)(b2 + lane * 4);
    float4 r;
    r.x = ax + bb.x; r.y = ay + bb.y; r.z = az + bb.z; r.w = aw + bb.w;
    *(float4*)(out + (size_t)n * N_CLS + lane * 4) = r;
}

// ---------------- launch ----------------
extern "C" void kernel_launch(void* const* d_in, const int* in_sizes, int n_in,
                              void* d_out, int out_size) {
    const float* x  = (const float*)d_in[0];
    const int*   ei = (const int*)d_in[1];
    const float* W1 = (const float*)d_in[2];
    const float* b1 = (const float*)d_in[3];
    const float* W2 = (const float*)d_in[4];
    const float* b2 = (const float*)d_in[5];
    float* out = (float*)d_out;

    float* out1;
    __nv_bfloat16 *wh, *wl;
    cudaGetSymbolAddress((void**)&out1, g_out1);
    cudaGetSymbolAddress((void**)&wh,   g_w1hi);
    cudaGetSymbolAddress((void**)&wl,   g_w1lo);

    static bool attrSet = false;
    if (!attrSet) {
        cudaFuncSetAttribute(k_gemm1_mma, cudaFuncAttributeMaxDynamicSharedMemorySize,
                             GEMM1_SMEM);
        attrSet = true;
    }

    k_prep<<<(N_NODES + 255) / 256, 256>>>(W1, W2);

    k_deg_count<<<(N_EDGES / 4 + 255) / 256, 256>>>(ei);
    k_scan1<<<NBLK, SCAN_B>>>();
    k_scan3<<<NBLK, SCAN_B>>>();
    k_csr_scatter<<<(N_EDGES / 4 + 255) / 256, 256>>>(ei);

    k_gemm1_mma<<<(N_NODES + 127) / 128, 256, GEMM1_SMEM>>>(x, wh, wl);
    k_agg1_gather<<<(N_NODES + 15) / 16, 256>>>(b1, out1);

    k_gemm2<<<(N_NODES + 127) / 128, 256>>>(out1);
    k_agg2_gather<<<(N_NODES + 15) / 16, 256>>>(b2, out);
}

// round 15
// speedup vs baseline: 1.3033x; 1.1314x over previous
#include <cuda_runtime.h>
#include <cuda_bf16.h>
#include <cuda_fp16.h>
#include <cstdint>

#define N_NODES 100000
#define N_FEATS 512
#define HIDDEN  64
#define N_CLS   40
#define N_EDGES 1600000
#define SCAN_B  1024
#define NBLK    ((N_NODES + SCAN_B - 1) / SCAN_B)   // 98

// ---------------- scratch ----------------
__device__ float  g_dinv[N_NODES];
__device__ __half g_h1h[(size_t)N_NODES * HIDDEN];   // fp16 hidden (layer 1)
__device__ float  g_out1[(size_t)N_NODES * HIDDEN];
__device__ __half g_h2h[(size_t)N_NODES * N_CLS];    // fp16 hidden (layer 2)
__device__ float  g_w2t[HIDDEN * N_CLS];             // [64][40]
__device__ __half g_w1hi[HIDDEN * N_FEATS];          // fp16 W1 hi
__device__ __half g_w1lo[HIDDEN * N_FEATS];          // fp16 W1 residual
__device__ int   g_deg[N_NODES];
__device__ int   g_rowptr[N_NODES];
__device__ int   g_cursor[N_NODES];
__device__ int   g_srcs[N_EDGES];
__device__ int   g_bsum[NBLK];

// ---------------- helpers ----------------
__device__ __forceinline__ uint32_t smem_u32(const void* p) {
    uint32_t a;
    asm("{ .reg .u64 t; cvta.to.shared.u64 t, %1; cvt.u32.u64 %0, t; }" : "=r"(a) : "l"(p));
    return a;
}
__device__ __forceinline__ void ldm_x4(uint32_t& r0, uint32_t& r1, uint32_t& r2,
                                       uint32_t& r3, uint32_t addr) {
    asm volatile("ldmatrix.sync.aligned.m8n8.x4.shared.b16 {%0,%1,%2,%3}, [%4];"
                 : "=r"(r0), "=r"(r1), "=r"(r2), "=r"(r3) : "r"(addr));
}
__device__ __forceinline__ void mma16816h(float* d, const uint32_t* a,
                                          uint32_t b0, uint32_t b1) {
    asm volatile(
        "mma.sync.aligned.m16n8k16.row.col.f32.f16.f16.f32 "
        "{%0,%1,%2,%3}, {%4,%5,%6,%7}, {%8,%9}, {%0,%1,%2,%3};"
        : "+f"(d[0]), "+f"(d[1]), "+f"(d[2]), "+f"(d[3])
        : "r"(a[0]), "r"(a[1]), "r"(a[2]), "r"(a[3]), "r"(b0), "r"(b1));
}
__device__ __forceinline__ void cp16(uint32_t dst, const void* src) {
    asm volatile("cp.async.cg.shared.global [%0], [%1], 16;" :: "r"(dst), "l"(src));
}
__device__ __forceinline__ void acc_h2(float& ax, float& ay, uint32_t h, float w) {
    float2 f = __half22float2(*(const __half2*)&h);
    ax += f.x * w; ay += f.y * w;
}

// ---------------- fused prep ----------------
__global__ void k_prep(const float* __restrict__ W1, const float* __restrict__ W2) {
    int i = blockIdx.x * blockDim.x + threadIdx.x;
    if (i < HIDDEN * N_FEATS) {
        float v = W1[i];
        __half h = __float2half_rn(v);
        g_w1hi[i] = h;
        g_w1lo[i] = __float2half_rn(v - __half2float(h));
    }
    if (i < HIDDEN * N_CLS) {
        int k = i / N_CLS, j = i - k * N_CLS;
        g_w2t[i] = W2[j * HIDDEN + k];
    }
    if (i < N_NODES) g_deg[i] = 0;
}

// ---------------- CSR build ----------------
__global__ void k_deg_count(const int* __restrict__ ei) {
    int e = (blockIdx.x * blockDim.x + threadIdx.x) * 4;
    if (e >= N_EDGES) return;
    int4 d = *(const int4*)(ei + N_EDGES + e);
    atomicAdd(&g_deg[d.x], 1);
    atomicAdd(&g_deg[d.y], 1);
    atomicAdd(&g_deg[d.z], 1);
    atomicAdd(&g_deg[d.w], 1);
}
__global__ void __launch_bounds__(SCAN_B) k_scan1() {
    int i = blockIdx.x * SCAN_B + threadIdx.x;
    int lane = threadIdx.x & 31, wid = threadIdx.x >> 5;
    int v = (i < N_NODES) ? g_deg[i] : 0;
#pragma unroll
    for (int o = 16; o > 0; o >>= 1) v += __shfl_down_sync(0xffffffffu, v, o);
    __shared__ int ws[32];
    if (lane == 0) ws[wid] = v;
    __syncthreads();
    if (wid == 0) {
        int t = ws[lane];
#pragma unroll
        for (int o = 16; o > 0; o >>= 1) t += __shfl_down_sync(0xffffffffu, t, o);
        if (lane == 0) g_bsum[blockIdx.x] = t;
    }
}
__global__ void __launch_bounds__(SCAN_B) k_scan3() {
    const int tid = threadIdx.x;
    const int lane = tid & 31, wid = tid >> 5;
    __shared__ int ws[32];
    __shared__ int s_boff;

    int bv = (tid < blockIdx.x && tid < NBLK) ? g_bsum[tid] : 0;
#pragma unroll
    for (int o = 16; o > 0; o >>= 1) bv += __shfl_down_sync(0xffffffffu, bv, o);
    if (lane == 0) ws[wid] = bv;
    __syncthreads();
    if (wid == 0) {
        int t = ws[lane];
#pragma unroll
        for (int o = 16; o > 0; o >>= 1) t += __shfl_down_sync(0xffffffffu, t, o);
        if (lane == 0) s_boff = t;
    }
    __syncthreads();

    int i = blockIdx.x * SCAN_B + tid;
    int d = (i < N_NODES) ? g_deg[i] : 0;
    int v = d;
#pragma unroll
    for (int o = 1; o < 32; o <<= 1) {
        int n = __shfl_up_sync(0xffffffffu, v, o);
        if (lane >= o) v += n;
    }
    __syncthreads();
    if (lane == 31) ws[wid] = v;
    __syncthreads();
    if (wid == 0) {
        int t = ws[lane];
#pragma unroll
        for (int o = 1; o < 32; o <<= 1) {
            int n = __shfl_up_sync(0xffffffffu, t, o);
            if (lane >= o) t += n;
        }
        ws[lane] = t;
    }
    __syncthreads();
    int excl = s_boff + ((wid > 0) ? ws[wid - 1] : 0) + (v - d);
    if (i < N_NODES) {
        g_rowptr[i] = excl;
        g_cursor[i] = excl;
        g_dinv[i]   = rsqrtf((float)d + 1.0f);
    }
}
__global__ void k_csr_scatter(const int* __restrict__ ei) {
    int e = (blockIdx.x * blockDim.x + threadIdx.x) * 4;
    if (e >= N_EDGES) return;
    int4 s = *(const int4*)(ei + e);
    int4 d = *(const int4*)(ei + N_EDGES + e);
    int p0 = atomicAdd(&g_cursor[d.x], 1); g_srcs[p0] = s.x;
    int p1 = atomicAdd(&g_cursor[d.y], 1); g_srcs[p1] = s.y;
    int p2 = atomicAdd(&g_cursor[d.z], 1); g_srcs[p2] = s.z;
    int p3 = atomicAdd(&g_cursor[d.w], 1); g_srcs[p3] = s.w;
}

// ---------------- GEMM1: fp16 x, fp16 W hi/lo split (2 products) ------------
// smem: A tiles (x fp16) 2 bufs x 18432B at 0; B tiles 2 bufs x 2 splits x 9216B
#define A_OFF(buf)      ((size_t)(buf) * 18432)
#define B_OFF(buf, sp)  (36864 + (size_t)((buf) * 2 + (sp)) * 9216)
#define GEMM1_SMEM      (36864 + 4 * 9216)   // 73728 B -> 2 CTA/SM possible

__device__ __forceinline__ void g1_cvt_store(const float4* xr, char* smem, int buf,
                                             int tid) {
    char* a = smem + A_OFF(buf);
#pragma unroll
    for (int i = 0; i < 8; i++) {
        int idx = tid + i * 256;
        int row = idx >> 4;
        int kq  = (idx & 15) * 4;
        float4 v = xr[i];
        __half2 p0 = __floats2half2_rn(v.x, v.y);
        __half2 p1 = __floats2half2_rn(v.z, v.w);
        size_t off = ((size_t)row * 72 + kq) * 2;
        *(uint2*)(a + off) = make_uint2(*(uint32_t*)&p0, *(uint32_t*)&p1);
    }
}

__device__ __forceinline__ void g1_ldg_x(const float* __restrict__ x, float4* xr,
                                         int rowBase, int c, int tid) {
#pragma unroll
    for (int i = 0; i < 8; i++) {
        int idx = tid + i * 256;
        int row = idx >> 4;
        int kq  = (idx & 15) * 4;
        int grow = rowBase + row;
        xr[i] = make_float4(0.f, 0.f, 0.f, 0.f);
        if (grow < N_NODES)
            xr[i] = *(const float4*)(x + (size_t)grow * N_FEATS + c * 64 + kq);
    }
}

__device__ __forceinline__ void g1_cpasync_w(const __half* __restrict__ wh,
                                             const __half* __restrict__ wl,
                                             uint32_t sb, int c, int buf, int tid) {
#pragma unroll
    for (int i = 0; i < 2; i++) {
        int idx = tid + i * 256;
        int n = idx >> 3, j = idx & 7;
        uint32_t off = (uint32_t)(((size_t)n * 72 + j * 8) * 2);
        cp16(sb + (uint32_t)B_OFF(buf, 0) + off, wh + (size_t)n * N_FEATS + c * 64 + j * 8);
        cp16(sb + (uint32_t)B_OFF(buf, 1) + off, wl + (size_t)n * N_FEATS + c * 64 + j * 8);
    }
    asm volatile("cp.async.commit_group;" ::: "memory");
}

__global__ void __launch_bounds__(256) k_gemm1_mma(const float* __restrict__ x,
                                                   const __half* __restrict__ wh,
                                                   const __half* __restrict__ wl) {
    extern __shared__ __align__(16) char smem[];
    const uint32_t sb = smem_u32(smem);
    const int tid = threadIdx.x, w = tid >> 5, lane = tid & 31;
    const int rowBase = blockIdx.x * 128;

    float acc[8][4];
#pragma unroll
    for (int s = 0; s < 8; s++)
#pragma unroll
        for (int j = 0; j < 4; j++) acc[s][j] = 0.f;

    {
        float4 xr[8];
        g1_ldg_x(x, xr, rowBase, 0, tid);
        g1_cpasync_w(wh, wl, sb, 0, 0, tid);
        g1_cvt_store(xr, smem, 0, tid);
        asm volatile("cp.async.wait_group 0;" ::: "memory");
    }
    __syncthreads();

    const int arow = w * 16 + (lane & 15);
    const int acolbase = ((lane >> 4) & 1) * 8;
    const int brow = (lane & 7) + ((lane >> 4) & 1) * 8;
    const int bcolbase = ((lane >> 3) & 1) * 8;

    int buf = 0;
    for (int c = 0; c < 8; c++) {
        float4 xr[8];
        if (c < 7) {
            g1_ldg_x(x, xr, rowBase, c + 1, tid);
            g1_cpasync_w(wh, wl, sb, c + 1, buf ^ 1, tid);
        }

        const uint32_t aT = sb + (uint32_t)A_OFF(buf);
        const uint32_t bH = sb + (uint32_t)B_OFF(buf, 0);
        const uint32_t bL = sb + (uint32_t)B_OFF(buf, 1);

#pragma unroll
        for (int t = 0; t < 4; t++) {
            int kk = t * 16;
            uint32_t ar[4];
            uint32_t aoff = (uint32_t)((arow * 72 + kk + acolbase) * 2);
            ldm_x4(ar[0], ar[1], ar[2], ar[3], aT + aoff);
#pragma unroll
            for (int p = 0; p < 4; p++) {
                int n0 = p * 16;
                uint32_t boff = (uint32_t)((((n0 + brow) * 72) + kk + bcolbase) * 2);
                uint32_t bh0, bh1, bh2, bh3, bl0, bl1, bl2, bl3;
                ldm_x4(bh0, bh1, bh2, bh3, bH + boff);
                ldm_x4(bl0, bl1, bl2, bl3, bL + boff);
                mma16816h(acc[2 * p],     ar, bh0, bh1);
                mma16816h(acc[2 * p],     ar, bl0, bl1);
                mma16816h(acc[2 * p + 1], ar, bh2, bh3);
                mma16816h(acc[2 * p + 1], ar, bl2, bl3);
            }
        }

        if (c < 7) {
            g1_cvt_store(xr, smem, buf ^ 1, tid);
            asm volatile("cp.async.wait_group 0;" ::: "memory");
        }
        __syncthreads();
        buf ^= 1;
    }

    // epilogue: write h1 as fp16
    const int r0 = rowBase + w * 16 + (lane >> 2);
    const int cb = (lane & 3) * 2;
#pragma unroll
    for (int s = 0; s < 8; s++) {
        int col = s * 8 + cb;
        if (r0 < N_NODES) {
            __half2 h = __floats2half2_rn(acc[s][0], acc[s][1]);
            *(__half2*)(g_h1h + (size_t)r0 * HIDDEN + col) = h;
        }
        if (r0 + 8 < N_NODES) {
            __half2 h = __floats2half2_rn(acc[s][2], acc[s][3]);
            *(__half2*)(g_h1h + (size_t)(r0 + 8) * HIDDEN + col) = h;
        }
    }
}

// ------- layer-1 aggregation: 16-lane groups over fp16 rows -----------------
__global__ void __launch_bounds__(256) k_agg1_gather(const float* __restrict__ b1,
                                                     float* __restrict__ out1) {
    const int tid  = threadIdx.x;
    const int g    = tid >> 4;
    const int lane = tid & 15;
    const int n    = blockIdx.x * 16 + g;
    if (n >= N_NODES) return;

    const float dn = g_dinv[n];
    const int start = g_rowptr[n];
    const int end   = start + g_deg[n];

    uint2 qn = *(const uint2*)(g_h1h + (size_t)n * HIDDEN + lane * 4);
    float s = dn * dn;
    float ax = 0.f, ay = 0.f, az = 0.f, aw = 0.f;
    acc_h2(ax, ay, qn.x, s);
    acc_h2(az, aw, qn.y, s);

    int e = start;
    for (; e + 4 <= end; e += 4) {
        int s0 = g_srcs[e], s1 = g_srcs[e + 1], s2 = g_srcs[e + 2], s3 = g_srcs[e + 3];
        float w0 = g_dinv[s0] * dn, w1 = g_dinv[s1] * dn;
        float w2 = g_dinv[s2] * dn, w3 = g_dinv[s3] * dn;
        uint2 m0 = *(const uint2*)(g_h1h + (size_t)s0 * HIDDEN + lane * 4);
        uint2 m1 = *(const uint2*)(g_h1h + (size_t)s1 * HIDDEN + lane * 4);
        uint2 m2 = *(const uint2*)(g_h1h + (size_t)s2 * HIDDEN + lane * 4);
        uint2 m3 = *(const uint2*)(g_h1h + (size_t)s3 * HIDDEN + lane * 4);
        acc_h2(ax, ay, m0.x, w0); acc_h2(az, aw, m0.y, w0);
        acc_h2(ax, ay, m1.x, w1); acc_h2(az, aw, m1.y, w1);
        acc_h2(ax, ay, m2.x, w2); acc_h2(az, aw, m2.y, w2);
        acc_h2(ax, ay, m3.x, w3); acc_h2(az, aw, m3.y, w3);
    }
    for (; e < end; e++) {
        int src = g_srcs[e];
        float w = g_dinv[src] * dn;
        uint2 m = *(const uint2*)(g_h1h + (size_t)src * HIDDEN + lane * 4);
        acc_h2(ax, ay, m.x, w); acc_h2(az, aw, m.y, w);
    }
    float4 bb = *(const float4*)(b1 + lane * 4);
    float4 r;
    r.x = fmaxf(ax + bb.x, 0.f);
    r.y = fmaxf(ay + bb.y, 0.f);
    r.z = fmaxf(az + bb.z, 0.f);
    r.w = fmaxf(aw + bb.w, 0.f);
    *(float4*)(out1 + (size_t)n * HIDDEN + lane * 4) = r;
}

// ---------------- GEMM2: h2h[N][40] = out1[N][64] @ W2^T (fp16 out) ---------
__global__ void __launch_bounds__(256) k_gemm2(const float* __restrict__ h1r) {
    __shared__ float xs[128][65];
    __shared__ float wsT[HIDDEN * N_CLS];
    const int tid = threadIdx.x;
    const int r = tid & 127;
    const int q = tid >> 7;
    const int rowBase = blockIdx.x * 128;

#pragma unroll
    for (int m = 0; m < 8; m++) {
        int idx4 = tid + m * 256;
        int row = idx4 >> 4, kq = (idx4 & 15) * 4;
        int grow = rowBase + row;
        float4 v = make_float4(0.f, 0.f, 0.f, 0.f);
        if (grow < N_NODES)
            v = *(const float4*)(h1r + (size_t)grow * HIDDEN + kq);
        xs[row][kq + 0] = v.x; xs[row][kq + 1] = v.y;
        xs[row][kq + 2] = v.z; xs[row][kq + 3] = v.w;
    }
    for (int idx4 = tid; idx4 < 640; idx4 += 256)
        ((float4*)wsT)[idx4] = ((const float4*)g_w2t)[idx4];
    __syncthreads();

    unsigned long long acc[10];
#pragma unroll
    for (int i = 0; i < 10; i++) acc[i] = 0ull;

#pragma unroll 4
    for (int k = 0; k < HIDDEN; k++) {
        float xv = xs[r][k];
        unsigned long long xx;
        asm("mov.b64 %0, {%1, %1};" : "=l"(xx) : "f"(xv));
        const unsigned long long* wrow =
            (const unsigned long long*)(wsT + k * N_CLS + q * 20);
#pragma unroll
        for (int c = 0; c < 10; c++) {
            unsigned long long w2 = wrow[c];
            asm("fma.rn.f32x2 %0, %1, %2, %0;" : "+l"(acc[c]) : "l"(w2), "l"(xx));
        }
    }

    int grow = rowBase + r;
    if (grow < N_NODES) {
        __half* dst = g_h2h + (size_t)grow * N_CLS + q * 20;
#pragma unroll
        for (int c = 0; c < 10; c++) {
            float a0, a1;
            asm("mov.b64 {%0,%1}, %2;" : "=f"(a0), "=f"(a1) : "l"(acc[c]));
            *(__half2*)(dst + c * 2) = __floats2half2_rn(a0, a1);
        }
    }
}

// ------- layer-2 aggregation: 16-lane groups over fp16 rows -----------------
__global__ void __launch_bounds__(256) k_agg2_gather(const float* __restrict__ b2,
                                                     float* __restrict__ out) {
    const int tid  = threadIdx.x;
    const int g    = tid >> 4;
    const int lane = tid & 15;
    const int n    = blockIdx.x * 16 + g;
    if (n >= N_NODES || lane >= 10) return;

    const float dn = g_dinv[n];
    const int start = g_rowptr[n];
    const int end   = start + g_deg[n];

    uint2 qn = *(const uint2*)(g_h2h + (size_t)n * N_CLS + lane * 4);
    float s = dn * dn;
    float ax = 0.f, ay = 0.f, az = 0.f, aw = 0.f;
    acc_h2(ax, ay, qn.x, s);
    acc_h2(az, aw, qn.y, s);

    int e = start;
    for (; e + 4 <= end; e += 4) {
        int s0 = g_srcs[e], s1 = g_srcs[e + 1], s2 = g_srcs[e + 2], s3 = g_srcs[e + 3];
        float w0 = g_dinv[s0] * dn, w1 = g_dinv[s1] * dn;
        float w2 = g_dinv[s2] * dn, w3 = g_dinv[s3] * dn;
        uint2 m0 = *(const uint2*)(g_h2h + (size_t)s0 * N_CLS + lane * 4);
        uint2 m1 = *(const uint2*)(g_h2h + (size_t)s1 * N_CLS + lane * 4);
        uint2 m2 = *(const uint2*)(g_h2h + (size_t)s2 * N_CLS + lane * 4);
        uint2 m3 = *(const uint2*)(g_h2h + (size_t)s3 * N_CLS + lane * 4);
        acc_h2(ax, ay, m0.x, w0); acc_h2(az, aw, m0.y, w0);
        acc_h2(ax, ay, m1.x, w1); acc_h2(az, aw, m1.y, w1);
        acc_h2(ax, ay, m2.x, w2); acc_h2(az, aw, m2.y, w2);
        acc_h2(ax, ay, m3.x, w3); acc_h2(az, aw, m3.y, w3);
    }
    for (; e < end; e++) {
        int src = g_srcs[e];
        float w = g_dinv[src] * dn;
        uint2 m = *(const uint2*)(g_h2h + (size_t)src * N_CLS + lane * 4);
        acc_h2(ax, ay, m.x, w); acc_h2(az, aw, m.y, w);
    }
    float4 bb = *(const float4*)(b2 + lane * 4);
    float4 r;
    r.x = ax + bb.x; r.y = ay + bb.y; r.z = az + bb.z; r.w = aw + bb.w;
    *(float4*)(out + (size_t)n * N_CLS + lane * 4) = r;
}

// ---------------- launch ----------------
extern "C" void kernel_launch(void* const* d_in, const int* in_sizes, int n_in,
                              void* d_out, int out_size) {
    const float* x  = (const float*)d_in[0];
    const int*   ei = (const int*)d_in[1];
    const float* W1 = (const float*)d_in[2];
    const float* b1 = (const float*)d_in[3];
    const float* W2 = (const float*)d_in[4];
    const float* b2 = (const float*)d_in[5];
    float* out = (float*)d_out;

    float* out1;
    __half *wh, *wl;
    cudaGetSymbolAddress((void**)&out1, g_out1);
    cudaGetSymbolAddress((void**)&wh,   g_w1hi);
    cudaGetSymbolAddress((void**)&wl,   g_w1lo);

    static bool attrSet = false;
    if (!attrSet) {
        cudaFuncSetAttribute(k_gemm1_mma, cudaFuncAttributeMaxDynamicSharedMemorySize,
                             GEMM1_SMEM);
        attrSet = true;
    }

    k_prep<<<(N_NODES + 255) / 256, 256>>>(W1, W2);

    k_deg_count<<<(N_EDGES / 4 + 255) / 256, 256>>>(ei);
    k_scan1<<<NBLK, SCAN_B>>>();
    k_scan3<<<NBLK, SCAN_B>>>();
    k_csr_scatter<<<(N_EDGES / 4 + 255) / 256, 256>>>(ei);

    k_gemm1_mma<<<(N_NODES + 127) / 128, 256, GEMM1_SMEM>>>(x, wh, wl);
    k_agg1_gather<<<(N_NODES + 15) / 16, 256>>>(b1, out1);

    k_gemm2<<<(N_NODES + 127) / 128, 256>>>(out1);
    k_agg2_gather<<<(N_NODES + 15) / 16, 256>>>(b2, out);
}

// round 16
// speedup vs baseline: 1.3077x; 1.0034x over previous
#include <cuda_runtime.h>
#include <cuda_bf16.h>
#include <cuda_fp16.h>
#include <cstdint>

#define N_NODES 100000
#define N_FEATS 512
#define HIDDEN  64
#define N_CLS   40
#define N_EDGES 1600000
#define SCAN_B  1024
#define NBLK    ((N_NODES + SCAN_B - 1) / SCAN_B)   // 98

// ---------------- scratch ----------------
__device__ float  g_dinv[N_NODES];
__device__ __half g_h1h[(size_t)N_NODES * HIDDEN];   // fp16 hidden (layer 1)
__device__ __half g_out1h[(size_t)N_NODES * HIDDEN]; // fp16 relu'd hidden
__device__ __half g_h2h[(size_t)N_NODES * N_CLS];    // fp16 hidden (layer 2)
__device__ float  g_w2t[HIDDEN * N_CLS];             // [64][40]
__device__ __half g_w1hi[HIDDEN * N_FEATS];          // fp16 W1 hi
__device__ __half g_w1lo[HIDDEN * N_FEATS];          // fp16 W1 residual
__device__ int   g_deg[N_NODES];
__device__ int   g_rowptr[N_NODES];
__device__ int   g_cursor[N_NODES];
__device__ int   g_srcs[N_EDGES];
__device__ int   g_bsum[NBLK];

// ---------------- helpers ----------------
__device__ __forceinline__ uint32_t smem_u32(const void* p) {
    uint32_t a;
    asm("{ .reg .u64 t; cvta.to.shared.u64 t, %1; cvt.u32.u64 %0, t; }" : "=r"(a) : "l"(p));
    return a;
}
__device__ __forceinline__ void ldm_x4(uint32_t& r0, uint32_t& r1, uint32_t& r2,
                                       uint32_t& r3, uint32_t addr) {
    asm volatile("ldmatrix.sync.aligned.m8n8.x4.shared.b16 {%0,%1,%2,%3}, [%4];"
                 : "=r"(r0), "=r"(r1), "=r"(r2), "=r"(r3) : "r"(addr));
}
__device__ __forceinline__ void mma16816h(float* d, const uint32_t* a,
                                          uint32_t b0, uint32_t b1) {
    asm volatile(
        "mma.sync.aligned.m16n8k16.row.col.f32.f16.f16.f32 "
        "{%0,%1,%2,%3}, {%4,%5,%6,%7}, {%8,%9}, {%0,%1,%2,%3};"
        : "+f"(d[0]), "+f"(d[1]), "+f"(d[2]), "+f"(d[3])
        : "r"(a[0]), "r"(a[1]), "r"(a[2]), "r"(a[3]), "r"(b0), "r"(b1));
}
__device__ __forceinline__ void cp16(uint32_t dst, const void* src) {
    asm volatile("cp.async.cg.shared.global [%0], [%1], 16;" :: "r"(dst), "l"(src));
}
__device__ __forceinline__ void acc_h2(float& ax, float& ay, uint32_t h, float w) {
    float2 f = __half22float2(*(const __half2*)&h);
    ax += f.x * w; ay += f.y * w;
}

// ---------------- fused prep ----------------
__global__ void k_prep(const float* __restrict__ W1, const float* __restrict__ W2) {
    int i = blockIdx.x * blockDim.x + threadIdx.x;
    if (i < HIDDEN * N_FEATS) {
        float v = W1[i];
        __half h = __float2half_rn(v);
        g_w1hi[i] = h;
        g_w1lo[i] = __float2half_rn(v - __half2float(h));
    }
    if (i < HIDDEN * N_CLS) {
        int k = i / N_CLS, j = i - k * N_CLS;
        g_w2t[i] = W2[j * HIDDEN + k];
    }
    if (i < N_NODES) g_deg[i] = 0;
}

// ---------------- CSR build ----------------
__global__ void k_deg_count(const int* __restrict__ ei) {
    int e = (blockIdx.x * blockDim.x + threadIdx.x) * 4;
    if (e >= N_EDGES) return;
    int4 d = *(const int4*)(ei + N_EDGES + e);
    atomicAdd(&g_deg[d.x], 1);
    atomicAdd(&g_deg[d.y], 1);
    atomicAdd(&g_deg[d.z], 1);
    atomicAdd(&g_deg[d.w], 1);
}
__global__ void __launch_bounds__(SCAN_B) k_scan1() {
    int i = blockIdx.x * SCAN_B + threadIdx.x;
    int lane = threadIdx.x & 31, wid = threadIdx.x >> 5;
    int v = (i < N_NODES) ? g_deg[i] : 0;
#pragma unroll
    for (int o = 16; o > 0; o >>= 1) v += __shfl_down_sync(0xffffffffu, v, o);
    __shared__ int ws[32];
    if (lane == 0) ws[wid] = v;
    __syncthreads();
    if (wid == 0) {
        int t = ws[lane];
#pragma unroll
        for (int o = 16; o > 0; o >>= 1) t += __shfl_down_sync(0xffffffffu, t, o);
        if (lane == 0) g_bsum[blockIdx.x] = t;
    }
}
__global__ void __launch_bounds__(SCAN_B) k_scan3() {
    const int tid = threadIdx.x;
    const int lane = tid & 31, wid = tid >> 5;
    __shared__ int ws[32];
    __shared__ int s_boff;

    int bv = (tid < blockIdx.x && tid < NBLK) ? g_bsum[tid] : 0;
#pragma unroll
    for (int o = 16; o > 0; o >>= 1) bv += __shfl_down_sync(0xffffffffu, bv, o);
    if (lane == 0) ws[wid] = bv;
    __syncthreads();
    if (wid == 0) {
        int t = ws[lane];
#pragma unroll
        for (int o = 16; o > 0; o >>= 1) t += __shfl_down_sync(0xffffffffu, t, o);
        if (lane == 0) s_boff = t;
    }
    __syncthreads();

    int i = blockIdx.x * SCAN_B + tid;
    int d = (i < N_NODES) ? g_deg[i] : 0;
    int v = d;
#pragma unroll
    for (int o = 1; o < 32; o <<= 1) {
        int n = __shfl_up_sync(0xffffffffu, v, o);
        if (lane >= o) v += n;
    }
    __syncthreads();
    if (lane == 31) ws[wid] = v;
    __syncthreads();
    if (wid == 0) {
        int t = ws[lane];
#pragma unroll
        for (int o = 1; o < 32; o <<= 1) {
            int n = __shfl_up_sync(0xffffffffu, t, o);
            if (lane >= o) t += n;
        }
        ws[lane] = t;
    }
    __syncthreads();
    int excl = s_boff + ((wid > 0) ? ws[wid - 1] : 0) + (v - d);
    if (i < N_NODES) {
        g_rowptr[i] = excl;
        g_cursor[i] = excl;
        g_dinv[i]   = rsqrtf((float)d + 1.0f);
    }
}
__global__ void k_csr_scatter(const int* __restrict__ ei) {
    int e = (blockIdx.x * blockDim.x + threadIdx.x) * 4;
    if (e >= N_EDGES) return;
    int4 s = *(const int4*)(ei + e);
    int4 d = *(const int4*)(ei + N_EDGES + e);
    int p0 = atomicAdd(&g_cursor[d.x], 1); g_srcs[p0] = s.x;
    int p1 = atomicAdd(&g_cursor[d.y], 1); g_srcs[p1] = s.y;
    int p2 = atomicAdd(&g_cursor[d.z], 1); g_srcs[p2] = s.z;
    int p3 = atomicAdd(&g_cursor[d.w], 1); g_srcs[p3] = s.w;
}

// ---------------- GEMM1: fp16 x, fp16 W hi/lo split (2 products) ------------
#define A_OFF(buf)      ((size_t)(buf) * 18432)
#define B_OFF(buf, sp)  (36864 + (size_t)((buf) * 2 + (sp)) * 9216)
#define GEMM1_SMEM      (36864 + 4 * 9216)   // 73728 B -> 2 CTA/SM

__device__ __forceinline__ void g1_cvt_store(const float4* xr, char* smem, int buf,
                                             int tid) {
    char* a = smem + A_OFF(buf);
#pragma unroll
    for (int i = 0; i < 8; i++) {
        int idx = tid + i * 256;
        int row = idx >> 4;
        int kq  = (idx & 15) * 4;
        float4 v = xr[i];
        __half2 p0 = __floats2half2_rn(v.x, v.y);
        __half2 p1 = __floats2half2_rn(v.z, v.w);
        size_t off = ((size_t)row * 72 + kq) * 2;
        *(uint2*)(a + off) = make_uint2(*(uint32_t*)&p0, *(uint32_t*)&p1);
    }
}

__device__ __forceinline__ void g1_ldg_x(const float* __restrict__ x, float4* xr,
                                         int rowBase, int c, int tid) {
#pragma unroll
    for (int i = 0; i < 8; i++) {
        int idx = tid + i * 256;
        int row = idx >> 4;
        int kq  = (idx & 15) * 4;
        int grow = rowBase + row;
        xr[i] = make_float4(0.f, 0.f, 0.f, 0.f);
        if (grow < N_NODES)
            xr[i] = *(const float4*)(x + (size_t)grow * N_FEATS + c * 64 + kq);
    }
}

__device__ __forceinline__ void g1_cpasync_w(const __half* __restrict__ wh,
                                             const __half* __restrict__ wl,
                                             uint32_t sb, int c, int buf, int tid) {
#pragma unroll
    for (int i = 0; i < 2; i++) {
        int idx = tid + i * 256;
        int n = idx >> 3, j = idx & 7;
        uint32_t off = (uint32_t)(((size_t)n * 72 + j * 8) * 2);
        cp16(sb + (uint32_t)B_OFF(buf, 0) + off, wh + (size_t)n * N_FEATS + c * 64 + j * 8);
        cp16(sb + (uint32_t)B_OFF(buf, 1) + off, wl + (size_t)n * N_FEATS + c * 64 + j * 8);
    }
    asm volatile("cp.async.commit_group;" ::: "memory");
}

__global__ void __launch_bounds__(256) k_gemm1_mma(const float* __restrict__ x,
                                                   const __half* __restrict__ wh,
                                                   const __half* __restrict__ wl) {
    extern __shared__ __align__(16) char smem[];
    const uint32_t sb = smem_u32(smem);
    const int tid = threadIdx.x, w = tid >> 5, lane = tid & 31;
    const int rowBase = blockIdx.x * 128;

    float acc[8][4];
#pragma unroll
    for (int s = 0; s < 8; s++)
#pragma unroll
        for (int j = 0; j < 4; j++) acc[s][j] = 0.f;

    {
        float4 xr[8];
        g1_ldg_x(x, xr, rowBase, 0, tid);
        g1_cpasync_w(wh, wl, sb, 0, 0, tid);
        g1_cvt_store(xr, smem, 0, tid);
        asm volatile("cp.async.wait_group 0;" ::: "memory");
    }
    __syncthreads();

    const int arow = w * 16 + (lane & 15);
    const int acolbase = ((lane >> 4) & 1) * 8;
    const int brow = (lane & 7) + ((lane >> 4) & 1) * 8;
    const int bcolbase = ((lane >> 3) & 1) * 8;

    int buf = 0;
    for (int c = 0; c < 8; c++) {
        float4 xr[8];
        if (c < 7) {
            g1_ldg_x(x, xr, rowBase, c + 1, tid);
            g1_cpasync_w(wh, wl, sb, c + 1, buf ^ 1, tid);
        }

        const uint32_t aT = sb + (uint32_t)A_OFF(buf);
        const uint32_t bH = sb + (uint32_t)B_OFF(buf, 0);
        const uint32_t bL = sb + (uint32_t)B_OFF(buf, 1);

#pragma unroll
        for (int t = 0; t < 4; t++) {
            int kk = t * 16;
            uint32_t ar[4];
            uint32_t aoff = (uint32_t)((arow * 72 + kk + acolbase) * 2);
            ldm_x4(ar[0], ar[1], ar[2], ar[3], aT + aoff);
#pragma unroll
            for (int p = 0; p < 4; p++) {
                int n0 = p * 16;
                uint32_t boff = (uint32_t)((((n0 + brow) * 72) + kk + bcolbase) * 2);
                uint32_t bh0, bh1, bh2, bh3, bl0, bl1, bl2, bl3;
                ldm_x4(bh0, bh1, bh2, bh3, bH + boff);
                ldm_x4(bl0, bl1, bl2, bl3, bL + boff);
                mma16816h(acc[2 * p],     ar, bh0, bh1);
                mma16816h(acc[2 * p],     ar, bl0, bl1);
                mma16816h(acc[2 * p + 1], ar, bh2, bh3);
                mma16816h(acc[2 * p + 1], ar, bl2, bl3);
            }
        }

        if (c < 7) {
            g1_cvt_store(xr, smem, buf ^ 1, tid);
            asm volatile("cp.async.wait_group 0;" ::: "memory");
        }
        __syncthreads();
        buf ^= 1;
    }

    // epilogue: write h1 as fp16
    const int r0 = rowBase + w * 16 + (lane >> 2);
    const int cb = (lane & 3) * 2;
#pragma unroll
    for (int s = 0; s < 8; s++) {
        int col = s * 8 + cb;
        if (r0 < N_NODES) {
            __half2 h = __floats2half2_rn(acc[s][0], acc[s][1]);
            *(__half2*)(g_h1h + (size_t)r0 * HIDDEN + col) = h;
        }
        if (r0 + 8 < N_NODES) {
            __half2 h = __floats2half2_rn(acc[s][2], acc[s][3]);
            *(__half2*)(g_h1h + (size_t)(r0 + 8) * HIDDEN + col) = h;
        }
    }
}

// ------- layer-1 aggregation: 16-lane groups over fp16 rows, fp16 out -------
__global__ void __launch_bounds__(256) k_agg1_gather(const float* __restrict__ b1) {
    const int tid  = threadIdx.x;
    const int g    = tid >> 4;
    const int lane = tid & 15;
    const int n    = blockIdx.x * 16 + g;
    if (n >= N_NODES) return;

    const float dn = g_dinv[n];
    const int start = g_rowptr[n];
    const int end   = start + g_deg[n];

    uint2 qn = *(const uint2*)(g_h1h + (size_t)n * HIDDEN + lane * 4);
    float s = dn * dn;
    float ax = 0.f, ay = 0.f, az = 0.f, aw = 0.f;
    acc_h2(ax, ay, qn.x, s);
    acc_h2(az, aw, qn.y, s);

    int e = start;
    for (; e + 4 <= end; e += 4) {
        int s0 = g_srcs[e], s1 = g_srcs[e + 1], s2 = g_srcs[e + 2], s3 = g_srcs[e + 3];
        float w0 = g_dinv[s0] * dn, w1 = g_dinv[s1] * dn;
        float w2 = g_dinv[s2] * dn, w3 = g_dinv[s3] * dn;
        uint2 m0 = *(const uint2*)(g_h1h + (size_t)s0 * HIDDEN + lane * 4);
        uint2 m1 = *(const uint2*)(g_h1h + (size_t)s1 * HIDDEN + lane * 4);
        uint2 m2 = *(const uint2*)(g_h1h + (size_t)s2 * HIDDEN + lane * 4);
        uint2 m3 = *(const uint2*)(g_h1h + (size_t)s3 * HIDDEN + lane * 4);
        acc_h2(ax, ay, m0.x, w0); acc_h2(az, aw, m0.y, w0);
        acc_h2(ax, ay, m1.x, w1); acc_h2(az, aw, m1.y, w1);
        acc_h2(ax, ay, m2.x, w2); acc_h2(az, aw, m2.y, w2);
        acc_h2(ax, ay, m3.x, w3); acc_h2(az, aw, m3.y, w3);
    }
    for (; e < end; e++) {
        int src = g_srcs[e];
        float w = g_dinv[src] * dn;
        uint2 m = *(const uint2*)(g_h1h + (size_t)src * HIDDEN + lane * 4);
        acc_h2(ax, ay, m.x, w); acc_h2(az, aw, m.y, w);
    }
    float4 bb = *(const float4*)(b1 + lane * 4);
    __half2 r0 = __floats2half2_rn(fmaxf(ax + bb.x, 0.f), fmaxf(ay + bb.y, 0.f));
    __half2 r1 = __floats2half2_rn(fmaxf(az + bb.z, 0.f), fmaxf(aw + bb.w, 0.f));
    *(uint2*)(g_out1h + (size_t)n * HIDDEN + lane * 4) =
        make_uint2(*(uint32_t*)&r0, *(uint32_t*)&r1);
}

// ---------------- GEMM2: h2h[N][40] = out1h[N][64] @ W2^T (fp16 in/out) -----
__global__ void __launch_bounds__(256) k_gemm2() {
    __shared__ float xs[128][65];
    __shared__ float wsT[HIDDEN * N_CLS];
    const int tid = threadIdx.x;
    const int r = tid & 127;
    const int q = tid >> 7;
    const int rowBase = blockIdx.x * 128;

#pragma unroll
    for (int m = 0; m < 8; m++) {
        int idx4 = tid + m * 256;
        int row = idx4 >> 4, kq = (idx4 & 15) * 4;
        int grow = rowBase + row;
        float2 f0 = make_float2(0.f, 0.f), f1 = make_float2(0.f, 0.f);
        if (grow < N_NODES) {
            uint2 v = *(const uint2*)(g_out1h + (size_t)grow * HIDDEN + kq);
            f0 = __half22float2(*(const __half2*)&v.x);
            f1 = __half22float2(*(const __half2*)&v.y);
        }
        xs[row][kq + 0] = f0.x; xs[row][kq + 1] = f0.y;
        xs[row][kq + 2] = f1.x; xs[row][kq + 3] = f1.y;
    }
    for (int idx4 = tid; idx4 < 640; idx4 += 256)
        ((float4*)wsT)[idx4] = ((const float4*)g_w2t)[idx4];
    __syncthreads();

    unsigned long long acc[10];
#pragma unroll
    for (int i = 0; i < 10; i++) acc[i] = 0ull;

#pragma unroll 4
    for (int k = 0; k < HIDDEN; k++) {
        float xv = xs[r][k];
        unsigned long long xx;
        asm("mov.b64 %0, {%1, %1};" : "=l"(xx) : "f"(xv));
        const unsigned long long* wrow =
            (const unsigned long long*)(wsT + k * N_CLS + q * 20);
#pragma unroll
        for (int c = 0; c < 10; c++) {
            unsigned long long w2 = wrow[c];
            asm("fma.rn.f32x2 %0, %1, %2, %0;" : "+l"(acc[c]) : "l"(w2), "l"(xx));
        }
    }

    int grow = rowBase + r;
    if (grow < N_NODES) {
        __half* dst = g_h2h + (size_t)grow * N_CLS + q * 20;
#pragma unroll
        for (int c = 0; c < 10; c++) {
            float a0, a1;
            asm("mov.b64 {%0,%1}, %2;" : "=f"(a0), "=f"(a1) : "l"(acc[c]));
            *(__half2*)(dst + c * 2) = __floats2half2_rn(a0, a1);
        }
    }
}

// ------- layer-2 aggregation: 16-lane groups over fp16 rows -----------------
__global__ void __launch_bounds__(256) k_agg2_gather(const float* __restrict__ b2,
                                                     float* __restrict__ out) {
    const int tid  = threadIdx.x;
    const int g    = tid >> 4;
    const int lane = tid & 15;
    const int n    = blockIdx.x * 16 + g;
    if (n >= N_NODES || lane >= 10) return;

    const float dn = g_dinv[n];
    const int start = g_rowptr[n];
    const int end   = start + g_deg[n];

    uint2 qn = *(const uint2*)(g_h2h + (size_t)n * N_CLS + lane * 4);
    float s = dn * dn;
    float ax = 0.f, ay = 0.f, az = 0.f, aw = 0.f;
    acc_h2(ax, ay, qn.x, s);
    acc_h2(az, aw, qn.y, s);

    int e = start;
    for (; e + 4 <= end; e += 4) {
        int s0 = g_srcs[e], s1 = g_srcs[e + 1], s2 = g_srcs[e + 2], s3 = g_srcs[e + 3];
        float w0 = g_dinv[s0] * dn, w1 = g_dinv[s1] * dn;
        float w2 = g_dinv[s2] * dn, w3 = g_dinv[s3] * dn;
        uint2 m0 = *(const uint2*)(g_h2h + (size_t)s0 * N_CLS + lane * 4);
        uint2 m1 = *(const uint2*)(g_h2h + (size_t)s1 * N_CLS + lane * 4);
        uint2 m2 = *(const uint2*)(g_h2h + (size_t)s2 * N_CLS + lane * 4);
        uint2 m3 = *(const uint2*)(g_h2h + (size_t)s3 * N_CLS + lane * 4);
        acc_h2(ax, ay, m0.x, w0); acc_h2(az, aw, m0.y, w0);
        acc_h2(ax, ay, m1.x, w1); acc_h2(az, aw, m1.y, w1);
        acc_h2(ax, ay, m2.x, w2); acc_h2(az, aw, m2.y, w2);
        acc_h2(ax, ay, m3.x, w3); acc_h2(az, aw, m3.y, w3);
    }
    for (; e < end; e++) {
        int src = g_srcs[e];
        float w = g_dinv[src] * dn;
        uint2 m = *(const uint2*)(g_h2h + (size_t)src * N_CLS + lane * 4);
        acc_h2(ax, ay, m.x, w); acc_h2(az, aw, m.y, w);
    }
    float4 bb = *(const float4*)(b2 + lane * 4);
    float4 r;
    r.x = ax + bb.x; r.y = ay + bb.y; r.z = az + bb.z; r.w = aw + bb.w;
    *(float4*)(out + (size_t)n * N_CLS + lane * 4) = r;
}

// ---------------- launch ----------------
extern "C" void kernel_launch(void* const* d_in, const int* in_sizes, int n_in,
                              void* d_out, int out_size) {
    const float* x  = (const float*)d_in[0];
    const int*   ei = (const int*)d_in[1];
    const float* W1 = (const float*)d_in[2];
    const float* b1 = (const float*)d_in[3];
    const float* W2 = (const float*)d_in[4];
    const float* b2 = (const float*)d_in[5];
    float* out = (float*)d_out;

    __half *wh, *wl;
    cudaGetSymbolAddress((void**)&wh, g_w1hi);
    cudaGetSymbolAddress((void**)&wl, g_w1lo);

    static bool attrSet = false;
    if (!attrSet) {
        cudaFuncSetAttribute(k_gemm1_mma, cudaFuncAttributeMaxDynamicSharedMemorySize,
                             GEMM1_SMEM);
        attrSet = true;
    }

    k_prep<<<(N_NODES + 255) / 256, 256>>>(W1, W2);

    k_deg_count<<<(N_EDGES / 4 + 255) / 256, 256>>>(ei);
    k_scan1<<<NBLK, SCAN_B>>>();
    k_scan3<<<NBLK, SCAN_B>>>();
    k_csr_scatter<<<(N_EDGES / 4 + 255) / 256, 256>>>(ei);

    k_gemm1_mma<<<(N_NODES + 127) / 128, 256, GEMM1_SMEM>>>(x, wh, wl);
    k_agg1_gather<<<(N_NODES + 15) / 16, 256>>>(b1);

    k_gemm2<<<(N_NODES + 127) / 128, 256>>>();
    k_agg2_gather<<<(N_NODES + 15) / 16, 256>>>(b2, out);
}

// round 17
// speedup vs baseline: 1.3887x; 1.0619x over previous
#include <cuda_runtime.h>
#include <cuda_bf16.h>
#include <cuda_fp16.h>
#include <cstdint>

#define N_NODES 100000
#define N_FEATS 512
#define HIDDEN  64
#define N_CLS   40
#define N_EDGES 1600000
#define SCAN_B  1024
#define NBLK    ((N_NODES + SCAN_B - 1) / SCAN_B)   // 98

// ---------------- scratch ----------------
__device__ float  g_dinv[N_NODES];
__device__ __half g_h1h[(size_t)N_NODES * HIDDEN];   // fp16 hidden (layer 1)
__device__ __half g_out1h[(size_t)N_NODES * HIDDEN]; // fp16 relu'd hidden
__device__ __half g_h2h[(size_t)N_NODES * N_CLS];    // fp16 hidden (layer 2)
__device__ __half g_w2hi[N_CLS * HIDDEN];            // fp16 W2 hi  [40][64]
__device__ __half g_w2lo[N_CLS * HIDDEN];            // fp16 W2 residual
__device__ __half g_w1hi[HIDDEN * N_FEATS];          // fp16 W1 hi
__device__ __half g_w1lo[HIDDEN * N_FEATS];          // fp16 W1 residual
__device__ int   g_deg[N_NODES];
__device__ int   g_rowptr[N_NODES];
__device__ int   g_cursor[N_NODES];
__device__ int   g_srcs[N_EDGES];
__device__ int   g_bsum[NBLK];

// ---------------- helpers ----------------
__device__ __forceinline__ uint32_t smem_u32(const void* p) {
    uint32_t a;
    asm("{ .reg .u64 t; cvta.to.shared.u64 t, %1; cvt.u32.u64 %0, t; }" : "=r"(a) : "l"(p));
    return a;
}
__device__ __forceinline__ void ldm_x4(uint32_t& r0, uint32_t& r1, uint32_t& r2,
                                       uint32_t& r3, uint32_t addr) {
    asm volatile("ldmatrix.sync.aligned.m8n8.x4.shared.b16 {%0,%1,%2,%3}, [%4];"
                 : "=r"(r0), "=r"(r1), "=r"(r2), "=r"(r3) : "r"(addr));
}
__device__ __forceinline__ void mma16816h(float* d, const uint32_t* a,
                                          uint32_t b0, uint32_t b1) {
    asm volatile(
        "mma.sync.aligned.m16n8k16.row.col.f32.f16.f16.f32 "
        "{%0,%1,%2,%3}, {%4,%5,%6,%7}, {%8,%9}, {%0,%1,%2,%3};"
        : "+f"(d[0]), "+f"(d[1]), "+f"(d[2]), "+f"(d[3])
        : "r"(a[0]), "r"(a[1]), "r"(a[2]), "r"(a[3]), "r"(b0), "r"(b1));
}
__device__ __forceinline__ void cp16(uint32_t dst, const void* src) {
    asm volatile("cp.async.cg.shared.global [%0], [%1], 16;" :: "r"(dst), "l"(src));
}
__device__ __forceinline__ void acc_h2(float& ax, float& ay, uint32_t h, float w) {
    float2 f = __half22float2(*(const __half2*)&h);
    ax += f.x * w; ay += f.y * w;
}

// ---------------- fused prep ----------------
__global__ void k_prep(const float* __restrict__ W1, const float* __restrict__ W2) {
    int i = blockIdx.x * blockDim.x + threadIdx.x;
    if (i < HIDDEN * N_FEATS) {
        float v = W1[i];
        __half h = __float2half_rn(v);
        g_w1hi[i] = h;
        g_w1lo[i] = __float2half_rn(v - __half2float(h));
    }
    if (i < N_CLS * HIDDEN) {          // W2 is [40][64] row-major = [n][k]
        float v = W2[i];
        __half h = __float2half_rn(v);
        g_w2hi[i] = h;
        g_w2lo[i] = __float2half_rn(v - __half2float(h));
    }
    if (i < N_NODES) g_deg[i] = 0;
}

// ---------------- CSR build ----------------
__global__ void k_deg_count(const int* __restrict__ ei) {
    int e = (blockIdx.x * blockDim.x + threadIdx.x) * 4;
    if (e >= N_EDGES) return;
    int4 d = *(const int4*)(ei + N_EDGES + e);
    atomicAdd(&g_deg[d.x], 1);
    atomicAdd(&g_deg[d.y], 1);
    atomicAdd(&g_deg[d.z], 1);
    atomicAdd(&g_deg[d.w], 1);
}
__global__ void __launch_bounds__(SCAN_B) k_scan1() {
    int i = blockIdx.x * SCAN_B + threadIdx.x;
    int lane = threadIdx.x & 31, wid = threadIdx.x >> 5;
    int v = (i < N_NODES) ? g_deg[i] : 0;
#pragma unroll
    for (int o = 16; o > 0; o >>= 1) v += __shfl_down_sync(0xffffffffu, v, o);
    __shared__ int ws[32];
    if (lane == 0) ws[wid] = v;
    __syncthreads();
    if (wid == 0) {
        int t = ws[lane];
#pragma unroll
        for (int o = 16; o > 0; o >>= 1) t += __shfl_down_sync(0xffffffffu, t, o);
        if (lane == 0) g_bsum[blockIdx.x] = t;
    }
}
__global__ void __launch_bounds__(SCAN_B) k_scan3() {
    const int tid = threadIdx.x;
    const int lane = tid & 31, wid = tid >> 5;
    __shared__ int ws[32];
    __shared__ int s_boff;

    int bv = (tid < blockIdx.x && tid < NBLK) ? g_bsum[tid] : 0;
#pragma unroll
    for (int o = 16; o > 0; o >>= 1) bv += __shfl_down_sync(0xffffffffu, bv, o);
    if (lane == 0) ws[wid] = bv;
    __syncthreads();
    if (wid == 0) {
        int t = ws[lane];
#pragma unroll
        for (int o = 16; o > 0; o >>= 1) t += __shfl_down_sync(0xffffffffu, t, o);
        if (lane == 0) s_boff = t;
    }
    __syncthreads();

    int i = blockIdx.x * SCAN_B + tid;
    int d = (i < N_NODES) ? g_deg[i] : 0;
    int v = d;
#pragma unroll
    for (int o = 1; o < 32; o <<= 1) {
        int n = __shfl_up_sync(0xffffffffu, v, o);
        if (lane >= o) v += n;
    }
    __syncthreads();
    if (lane == 31) ws[wid] = v;
    __syncthreads();
    if (wid == 0) {
        int t = ws[lane];
#pragma unroll
        for (int o = 1; o < 32; o <<= 1) {
            int n = __shfl_up_sync(0xffffffffu, t, o);
            if (lane >= o) t += n;
        }
        ws[lane] = t;
    }
    __syncthreads();
    int excl = s_boff + ((wid > 0) ? ws[wid - 1] : 0) + (v - d);
    if (i < N_NODES) {
        g_rowptr[i] = excl;
        g_cursor[i] = excl;
        g_dinv[i]   = rsqrtf((float)d + 1.0f);
    }
}
__global__ void k_csr_scatter(const int* __restrict__ ei) {
    int e = (blockIdx.x * blockDim.x + threadIdx.x) * 4;
    if (e >= N_EDGES) return;
    int4 s = *(const int4*)(ei + e);
    int4 d = *(const int4*)(ei + N_EDGES + e);
    int p0 = atomicAdd(&g_cursor[d.x], 1); g_srcs[p0] = s.x;
    int p1 = atomicAdd(&g_cursor[d.y], 1); g_srcs[p1] = s.y;
    int p2 = atomicAdd(&g_cursor[d.z], 1); g_srcs[p2] = s.z;
    int p3 = atomicAdd(&g_cursor[d.w], 1); g_srcs[p3] = s.w;
}

// ---------------- GEMM1: fp16 x, fp16 W hi/lo split (2 products) ------------
#define A_OFF(buf)      ((size_t)(buf) * 18432)
#define B_OFF(buf, sp)  (36864 + (size_t)((buf) * 2 + (sp)) * 9216)
#define GEMM1_SMEM      (36864 + 4 * 9216)   // 73728 B -> 2 CTA/SM

__device__ __forceinline__ void g1_cvt_store(const float4* xr, char* smem, int buf,
                                             int tid) {
    char* a = smem + A_OFF(buf);
#pragma unroll
    for (int i = 0; i < 8; i++) {
        int idx = tid + i * 256;
        int row = idx >> 4;
        int kq  = (idx & 15) * 4;
        float4 v = xr[i];
        __half2 p0 = __floats2half2_rn(v.x, v.y);
        __half2 p1 = __floats2half2_rn(v.z, v.w);
        size_t off = ((size_t)row * 72 + kq) * 2;
        *(uint2*)(a + off) = make_uint2(*(uint32_t*)&p0, *(uint32_t*)&p1);
    }
}

__device__ __forceinline__ void g1_ldg_x(const float* __restrict__ x, float4* xr,
                                         int rowBase, int c, int tid) {
#pragma unroll
    for (int i = 0; i < 8; i++) {
        int idx = tid + i * 256;
        int row = idx >> 4;
        int kq  = (idx & 15) * 4;
        int grow = rowBase + row;
        xr[i] = make_float4(0.f, 0.f, 0.f, 0.f);
        if (grow < N_NODES)
            xr[i] = *(const float4*)(x + (size_t)grow * N_FEATS + c * 64 + kq);
    }
}

__device__ __forceinline__ void g1_cpasync_w(const __half* __restrict__ wh,
                                             const __half* __restrict__ wl,
                                             uint32_t sb, int c, int buf, int tid) {
#pragma unroll
    for (int i = 0; i < 2; i++) {
        int idx = tid + i * 256;
        int n = idx >> 3, j = idx & 7;
        uint32_t off = (uint32_t)(((size_t)n * 72 + j * 8) * 2);
        cp16(sb + (uint32_t)B_OFF(buf, 0) + off, wh + (size_t)n * N_FEATS + c * 64 + j * 8);
        cp16(sb + (uint32_t)B_OFF(buf, 1) + off, wl + (size_t)n * N_FEATS + c * 64 + j * 8);
    }
    asm volatile("cp.async.commit_group;" ::: "memory");
}

__global__ void __launch_bounds__(256) k_gemm1_mma(const float* __restrict__ x,
                                                   const __half* __restrict__ wh,
                                                   const __half* __restrict__ wl) {
    extern __shared__ __align__(16) char smem[];
    const uint32_t sb = smem_u32(smem);
    const int tid = threadIdx.x, w = tid >> 5, lane = tid & 31;
    const int rowBase = blockIdx.x * 128;

    float acc[8][4];
#pragma unroll
    for (int s = 0; s < 8; s++)
#pragma unroll
        for (int j = 0; j < 4; j++) acc[s][j] = 0.f;

    {
        float4 xr[8];
        g1_ldg_x(x, xr, rowBase, 0, tid);
        g1_cpasync_w(wh, wl, sb, 0, 0, tid);
        g1_cvt_store(xr, smem, 0, tid);
        asm volatile("cp.async.wait_group 0;" ::: "memory");
    }
    __syncthreads();

    const int arow = w * 16 + (lane & 15);
    const int acolbase = ((lane >> 4) & 1) * 8;
    const int brow = (lane & 7) + ((lane >> 4) & 1) * 8;
    const int bcolbase = ((lane >> 3) & 1) * 8;

    int buf = 0;
    for (int c = 0; c < 8; c++) {
        float4 xr[8];
        if (c < 7) {
            g1_ldg_x(x, xr, rowBase, c + 1, tid);
            g1_cpasync_w(wh, wl, sb, c + 1, buf ^ 1, tid);
        }

        const uint32_t aT = sb + (uint32_t)A_OFF(buf);
        const uint32_t bH = sb + (uint32_t)B_OFF(buf, 0);
        const uint32_t bL = sb + (uint32_t)B_OFF(buf, 1);

#pragma unroll
        for (int t = 0; t < 4; t++) {
            int kk = t * 16;
            uint32_t ar[4];
            uint32_t aoff = (uint32_t)((arow * 72 + kk + acolbase) * 2);
            ldm_x4(ar[0], ar[1], ar[2], ar[3], aT + aoff);
#pragma unroll
            for (int p = 0; p < 4; p++) {
                int n0 = p * 16;
                uint32_t boff = (uint32_t)((((n0 + brow) * 72) + kk + bcolbase) * 2);
                uint32_t bh0, bh1, bh2, bh3, bl0, bl1, bl2, bl3;
                ldm_x4(bh0, bh1, bh2, bh3, bH + boff);
                ldm_x4(bl0, bl1, bl2, bl3, bL + boff);
                mma16816h(acc[2 * p],     ar, bh0, bh1);
                mma16816h(acc[2 * p],     ar, bl0, bl1);
                mma16816h(acc[2 * p + 1], ar, bh2, bh3);
                mma16816h(acc[2 * p + 1], ar, bl2, bl3);
            }
        }

        if (c < 7) {
            g1_cvt_store(xr, smem, buf ^ 1, tid);
            asm volatile("cp.async.wait_group 0;" ::: "memory");
        }
        __syncthreads();
        buf ^= 1;
    }

    // epilogue: write h1 as fp16
    const int r0 = rowBase + w * 16 + (lane >> 2);
    const int cb = (lane & 3) * 2;
#pragma unroll
    for (int s = 0; s < 8; s++) {
        int col = s * 8 + cb;
        if (r0 < N_NODES) {
            __half2 h = __floats2half2_rn(acc[s][0], acc[s][1]);
            *(__half2*)(g_h1h + (size_t)r0 * HIDDEN + col) = h;
        }
        if (r0 + 8 < N_NODES) {
            __half2 h = __floats2half2_rn(acc[s][2], acc[s][3]);
            *(__half2*)(g_h1h + (size_t)(r0 + 8) * HIDDEN + col) = h;
        }
    }
}

// ------- layer-1 aggregation: 16-lane groups over fp16 rows, fp16 out -------
__global__ void __launch_bounds__(256) k_agg1_gather(const float* __restrict__ b1) {
    const int tid  = threadIdx.x;
    const int g    = tid >> 4;
    const int lane = tid & 15;
    const int n    = blockIdx.x * 16 + g;
    if (n >= N_NODES) return;

    const float dn = g_dinv[n];
    const int start = g_rowptr[n];
    const int end   = start + g_deg[n];

    uint2 qn = *(const uint2*)(g_h1h + (size_t)n * HIDDEN + lane * 4);
    float s = dn * dn;
    float ax = 0.f, ay = 0.f, az = 0.f, aw = 0.f;
    acc_h2(ax, ay, qn.x, s);
    acc_h2(az, aw, qn.y, s);

    int e = start;
    for (; e + 4 <= end; e += 4) {
        int s0 = g_srcs[e], s1 = g_srcs[e + 1], s2 = g_srcs[e + 2], s3 = g_srcs[e + 3];
        float w0 = g_dinv[s0] * dn, w1 = g_dinv[s1] * dn;
        float w2 = g_dinv[s2] * dn, w3 = g_dinv[s3] * dn;
        uint2 m0 = *(const uint2*)(g_h1h + (size_t)s0 * HIDDEN + lane * 4);
        uint2 m1 = *(const uint2*)(g_h1h + (size_t)s1 * HIDDEN + lane * 4);
        uint2 m2 = *(const uint2*)(g_h1h + (size_t)s2 * HIDDEN + lane * 4);
        uint2 m3 = *(const uint2*)(g_h1h + (size_t)s3 * HIDDEN + lane * 4);
        acc_h2(ax, ay, m0.x, w0); acc_h2(az, aw, m0.y, w0);
        acc_h2(ax, ay, m1.x, w1); acc_h2(az, aw, m1.y, w1);
        acc_h2(ax, ay, m2.x, w2); acc_h2(az, aw, m2.y, w2);
        acc_h2(ax, ay, m3.x, w3); acc_h2(az, aw, m3.y, w3);
    }
    for (; e < end; e++) {
        int src = g_srcs[e];
        float w = g_dinv[src] * dn;
        uint2 m = *(const uint2*)(g_h1h + (size_t)src * HIDDEN + lane * 4);
        acc_h2(ax, ay, m.x, w); acc_h2(az, aw, m.y, w);
    }
    float4 bb = *(const float4*)(b1 + lane * 4);
    __half2 r0 = __floats2half2_rn(fmaxf(ax + bb.x, 0.f), fmaxf(ay + bb.y, 0.f));
    __half2 r1 = __floats2half2_rn(fmaxf(az + bb.z, 0.f), fmaxf(aw + bb.w, 0.f));
    *(uint2*)(g_out1h + (size_t)n * HIDDEN + lane * 4) =
        make_uint2(*(uint32_t*)&r0, *(uint32_t*)&r1);
}

// ---------------- GEMM2 (HMMA): h2h[N][40] = out1h[N][64] @ W2^T ------------
// single K=64 tile; A: 128x64 fp16 (72-pad), B: 48x64 fp16 hi/lo (72-pad, rows
// 40..47 zero). 8 warps x m16; 3 n16 groups x 4 ksteps x 2 products.
#define G2_A_OFF 0                    // 128*144 = 18432 B
#define G2_B_OFF(sp) (18432 + (size_t)(sp) * 6912)   // 48*144 each
#define GEMM2_SMEM (18432 + 2 * 6912)  // 32256 B

__global__ void __launch_bounds__(256) k_gemm2_mma() {
    extern __shared__ __align__(16) char smem2[];
    const uint32_t sb = smem_u32(smem2);
    const int tid = threadIdx.x, w = tid >> 5, lane = tid & 31;
    const int rowBase = blockIdx.x * 128;

    // zero B pad rows (40..47) hi+lo: 8 rows x 9 uint4 x 2 = 144 slots
    for (int i = tid; i < 144; i += 256) {
        int sp = i / 72, r = (i % 72) / 9, j = i % 9;
        *(uint4*)(smem2 + G2_B_OFF(sp) + (size_t)(40 + r) * 144 + j * 16) =
            make_uint4(0, 0, 0, 0);
    }
    // stage A: 128 rows x 8 uint4 = 1024 slots (cp.async)
    for (int i = tid; i < 1024; i += 256) {
        int row = i >> 3, j = i & 7;
        int grow = rowBase + row;
        uint32_t dst = sb + (uint32_t)(G2_A_OFF + (size_t)row * 144 + j * 16);
        if (grow < N_NODES)
            cp16(dst, g_out1h + (size_t)grow * HIDDEN + j * 8);
        else
            *(uint4*)(smem2 + G2_A_OFF + (size_t)row * 144 + j * 16) = make_uint4(0, 0, 0, 0);
    }
    // stage B: 40 rows x 8 uint4 x 2 splits = 640 slots
    for (int i = tid; i < 640; i += 256) {
        int sp = i / 320, r = (i % 320) >> 3, j = i & 7;
        uint32_t dst = sb + (uint32_t)(G2_B_OFF(sp) + (size_t)r * 144 + j * 16);
        const __half* src = (sp == 0 ? g_w2hi : g_w2lo) + (size_t)r * HIDDEN + j * 8;
        cp16(dst, src);
    }
    asm volatile("cp.async.commit_group;" ::: "memory");
    asm volatile("cp.async.wait_group 0;" ::: "memory");
    __syncthreads();

    float acc[6][4];
#pragma unroll
    for (int s = 0; s < 6; s++)
#pragma unroll
        for (int j = 0; j < 4; j++) acc[s][j] = 0.f;

    const int arow = w * 16 + (lane & 15);
    const int acolbase = ((lane >> 4) & 1) * 8;
    const int brow = (lane & 7) + ((lane >> 4) & 1) * 8;
    const int bcolbase = ((lane >> 3) & 1) * 8;

    const uint32_t aT = sb + (uint32_t)G2_A_OFF;
    const uint32_t bH = sb + (uint32_t)G2_B_OFF(0);
    const uint32_t bL = sb + (uint32_t)G2_B_OFF(1);

#pragma unroll
    for (int t = 0; t < 4; t++) {
        int kk = t * 16;
        uint32_t ar[4];
        uint32_t aoff = (uint32_t)((arow * 72 + kk + acolbase) * 2);
        ldm_x4(ar[0], ar[1], ar[2], ar[3], aT + aoff);
#pragma unroll
        for (int p = 0; p < 3; p++) {
            int n0 = p * 16;
            uint32_t boff = (uint32_t)((((n0 + brow) * 72) + kk + bcolbase) * 2);
            uint32_t bh0, bh1, bh2, bh3, bl0, bl1, bl2, bl3;
            ldm_x4(bh0, bh1, bh2, bh3, bH + boff);
            ldm_x4(bl0, bl1, bl2, bl3, bL + boff);
            mma16816h(acc[2 * p],     ar, bh0, bh1);
            mma16816h(acc[2 * p],     ar, bl0, bl1);
            mma16816h(acc[2 * p + 1], ar, bh2, bh3);
            mma16816h(acc[2 * p + 1], ar, bl2, bl3);
        }
    }

    // epilogue: store h2h fp16 (cols 0..39 only)
    const int r0 = rowBase + w * 16 + (lane >> 2);
    const int cb = (lane & 3) * 2;
#pragma unroll
    for (int s = 0; s < 5; s++) {          // tiles 0..4 cover cols 0..39
        int col = s * 8 + cb;
        if (r0 < N_NODES) {
            __half2 h = __floats2half2_rn(acc[s][0], acc[s][1]);
            *(__half2*)(g_h2h + (size_t)r0 * N_CLS + col) = h;
        }
        if (r0 + 8 < N_NODES) {
            __half2 h = __floats2half2_rn(acc[s][2], acc[s][3]);
            *(__half2*)(g_h2h + (size_t)(r0 + 8) * N_CLS + col) = h;
        }
    }
}

// ------- layer-2 aggregation: 16-lane groups over fp16 rows -----------------
__global__ void __launch_bounds__(256) k_agg2_gather(const float* __restrict__ b2,
                                                     float* __restrict__ out) {
    const int tid  = threadIdx.x;
    const int g    = tid >> 4;
    const int lane = tid & 15;
    const int n    = blockIdx.x * 16 + g;
    if (n >= N_NODES || lane >= 10) return;

    const float dn = g_dinv[n];
    const int start = g_rowptr[n];
    const int end   = start + g_deg[n];

    uint2 qn = *(const uint2*)(g_h2h + (size_t)n * N_CLS + lane * 4);
    float s = dn * dn;
    float ax = 0.f, ay = 0.f, az = 0.f, aw = 0.f;
    acc_h2(ax, ay, qn.x, s);
    acc_h2(az, aw, qn.y, s);

    int e = start;
    for (; e + 4 <= end; e += 4) {
        int s0 = g_srcs[e], s1 = g_srcs[e + 1], s2 = g_srcs[e + 2], s3 = g_srcs[e + 3];
        float w0 = g_dinv[s0] * dn, w1 = g_dinv[s1] * dn;
        float w2 = g_dinv[s2] * dn, w3 = g_dinv[s3] * dn;
        uint2 m0 = *(const uint2*)(g_h2h + (size_t)s0 * N_CLS + lane * 4);
        uint2 m1 = *(const uint2*)(g_h2h + (size_t)s1 * N_CLS + lane * 4);
        uint2 m2 = *(const uint2*)(g_h2h + (size_t)s2 * N_CLS + lane * 4);
        uint2 m3 = *(const uint2*)(g_h2h + (size_t)s3 * N_CLS + lane * 4);
        acc_h2(ax, ay, m0.x, w0); acc_h2(az, aw, m0.y, w0);
        acc_h2(ax, ay, m1.x, w1); acc_h2(az, aw, m1.y, w1);
        acc_h2(ax, ay, m2.x, w2); acc_h2(az, aw, m2.y, w2);
        acc_h2(ax, ay, m3.x, w3); acc_h2(az, aw, m3.y, w3);
    }
    for (; e < end; e++) {
        int src = g_srcs[e];
        float w = g_dinv[src] * dn;
        uint2 m = *(const uint2*)(g_h2h + (size_t)src * N_CLS + lane * 4);
        acc_h2(ax, ay, m.x, w); acc_h2(az, aw, m.y, w);
    }
    float4 bb = *(const float4*)(b2 + lane * 4);
    float4 r;
    r.x = ax + bb.x; r.y = ay + bb.y; r.z = az + bb.z; r.w = aw + bb.w;
    *(float4*)(out + (size_t)n * N_CLS + lane * 4) = r;
}

// ---------------- launch ----------------
extern "C" void kernel_launch(void* const* d_in, const int* in_sizes, int n_in,
                              void* d_out, int out_size) {
    const float* x  = (const float*)d_in[0];
    const int*   ei = (const int*)d_in[1];
    const float* W1 = (const float*)d_in[2];
    const float* b1 = (const float*)d_in[3];
    const float* W2 = (const float*)d_in[4];
    const float* b2 = (const float*)d_in[5];
    float* out = (float*)d_out;

    __half *wh, *wl;
    cudaGetSymbolAddress((void**)&wh, g_w1hi);
    cudaGetSymbolAddress((void**)&wl, g_w1lo);

    static bool attrSet = false;
    if (!attrSet) {
        cudaFuncSetAttribute(k_gemm1_mma, cudaFuncAttributeMaxDynamicSharedMemorySize,
                             GEMM1_SMEM);
        cudaFuncSetAttribute(k_gemm2_mma, cudaFuncAttributeMaxDynamicSharedMemorySize,
                             GEMM2_SMEM);
        attrSet = true;
    }

    k_prep<<<(N_NODES + 255) / 256, 256>>>(W1, W2);

    k_deg_count<<<(N_EDGES / 4 + 255) / 256, 256>>>(ei);
    k_scan1<<<NBLK, SCAN_B>>>();
    k_scan3<<<NBLK, SCAN_B>>>();
    k_csr_scatter<<<(N_EDGES / 4 + 255) / 256, 256>>>(ei);

    k_gemm1_mma<<<(N_NODES + 127) / 128, 256, GEMM1_SMEM>>>(x, wh, wl);
    k_agg1_gather<<<(N_NODES + 15) / 16, 256>>>(b1);

    k_gemm2_mma<<<(N_NODES + 127) / 128, 256, GEMM2_SMEM>>>();
    k_agg2_gather<<<(N_NODES + 15) / 16, 256>>>(b2, out);
}